// round 3
// baseline (speedup 1.0000x reference)
#include <cuda_runtime.h>
#include <math.h>
#include <stdint.h>

// Problem constants
#define BB   2
#define SS   2048
#define EE   1024
#define HH   16
#define DD   64
#define NTOK (BB * SS)   // 4096

// GEMM tiling
#define BM 128
#define BN 128
#define BK 32
#define NITER (EE / BK)          // 32
#define STAGE_U32 8192           // A 4096 + B 4096 uint32 per stage
#define GEMM_SMEM_BYTES (2 * STAGE_U32 * 4)   // 64 KB

// ---------------------------------------------------------------------------
// Scratch (device globals — no allocation allowed in kernel_launch)
// ---------------------------------------------------------------------------
__device__ float g_q[BB * HH * SS * DD];     // [B,H,S,D]
__device__ float g_k[BB * HH * SS * DD];
__device__ float g_v[BB * HH * SS * DD];
__device__ float g_attn[NTOK * EE];          // [B,S,E]

// ---------------------------------------------------------------------------
// tf32 helpers
// ---------------------------------------------------------------------------
__device__ __forceinline__ uint32_t f2tf32(float f)
{
    uint32_t u;
    asm("cvt.rna.tf32.f32 %0, %1;" : "=r"(u) : "f"(f));
    return u;
}

__device__ __forceinline__ void mma_tf32(float c[4], const uint32_t a[4],
                                         const uint32_t b[2])
{
    asm volatile(
        "mma.sync.aligned.m16n8k8.row.col.f32.tf32.tf32.f32 "
        "{%0,%1,%2,%3}, {%4,%5,%6,%7}, {%8,%9}, {%0,%1,%2,%3};"
        : "+f"(c[0]), "+f"(c[1]), "+f"(c[2]), "+f"(c[3])
        : "r"(a[0]), "r"(a[1]), "r"(a[2]), "r"(a[3]), "r"(b[0]), "r"(b[1]));
}

// ---------------------------------------------------------------------------
// tf32 MMA GEMM core: one BMxBN tile of A[4096,1024] @ W[1024,1024].
// 256 threads = 8 warps (2x4), warp tile 64x32, mma m16n8k8.
// Smem holds operands pre-permuted into fragment order:
//   A subtile (m16 x k8) = 128 u32: lane*4 + reg     (LDS.128 to read)
//   B subtile (k8 x n8)  =  64 u32: lane*2 + reg     (LDS.64 to read)
// Double-buffered, register-staged LDG, one barrier per k-iter.
// ---------------------------------------------------------------------------
__device__ __forceinline__ void gemm_mma_tile(const float* __restrict__ A,
                                              const float* __restrict__ W,
                                              float c[4][4][4],
                                              uint32_t* sm)
{
    const int tid = threadIdx.x;
    const int brow = blockIdx.y * BM;
    const int bcol = blockIdx.x * BN;
    const int w = tid >> 5, l = tid & 31;
    const int wm = w >> 2, wn = w & 3;

    // ---- gmem->smem mapping (4 float4 of A + 4 float4 of B per thread) ----
    const float* a_ptr[4];
    const float* b_ptr[4];
    int a_sts[4], b_sts[4];
#pragma unroll
    for (int j = 0; j < 4; j++) {
        int p = tid + 256 * j;
        // A: 128 rows x 8 float4
        {
            int row = p >> 3, c4 = p & 7, col = c4 * 4;
            a_ptr[j] = A + (size_t)(brow + row) * EE + col;
            int sub = (row >> 4) * 4 + (col >> 3);
            int reg = (((col & 7) >= 4) ? 2 : 0) + (((row & 15) >= 8) ? 1 : 0);
            a_sts[j] = sub * 128 + (row & 7) * 16 + reg;   // + t*4
        }
        // B: 32 rows x 32 float4
        {
            int krow = p >> 5, c4 = p & 31, n = c4 * 4;
            b_ptr[j] = W + (size_t)krow * EE + bcol + n;
            int sub = (krow >> 3) * 16 + (n >> 3);
            int kk = krow & 7;
            b_sts[j] = sub * 64 + ((c4 & 1) * 4) * 8 + (kk & 3) * 2 + (kk >> 2); // + t*8
        }
    }

#pragma unroll
    for (int mi = 0; mi < 4; mi++)
#pragma unroll
        for (int ni = 0; ni < 4; ni++)
#pragma unroll
            for (int r = 0; r < 4; r++) c[mi][ni][r] = 0.f;

    float4 av[4], bv[4];
#pragma unroll
    for (int j = 0; j < 4; j++) {
        av[j] = *(const float4*)(a_ptr[j]);
        bv[j] = *(const float4*)(b_ptr[j]);
    }
    // stage 0 store
    {
        uint32_t* sA = sm;
        uint32_t* sB = sm + 4096;
#pragma unroll
        for (int j = 0; j < 4; j++) {
            const float* af = (const float*)&av[j];
            const float* bf = (const float*)&bv[j];
#pragma unroll
            for (int t = 0; t < 4; t++) sA[a_sts[j] + t * 4] = f2tf32(af[t]);
#pragma unroll
            for (int t = 0; t < 4; t++) sB[b_sts[j] + t * 8] = f2tf32(bf[t]);
        }
    }
    __syncthreads();

    for (int it = 0; it < NITER; it++) {
        if (it + 1 < NITER) {
#pragma unroll
            for (int j = 0; j < 4; j++) {
                av[j] = *(const float4*)(a_ptr[j] + (it + 1) * BK);
                bv[j] = *(const float4*)(b_ptr[j] + (size_t)(it + 1) * BK * EE);
            }
        }

        // compute on current stage
        {
            const uint32_t* sA = sm + (it & 1) * STAGE_U32;
            const uint32_t* sB = sA + 4096;
#pragma unroll
            for (int ks = 0; ks < 4; ks++) {
                uint32_t a[4][4], b[4][2];
#pragma unroll
                for (int mi = 0; mi < 4; mi++) {
                    int sub = (wm * 4 + mi) * 4 + ks;
                    *(uint4*)a[mi] = *(const uint4*)&sA[sub * 128 + l * 4];
                }
#pragma unroll
                for (int ni = 0; ni < 4; ni++) {
                    int sub = ks * 16 + wn * 4 + ni;
                    *(uint2*)b[ni] = *(const uint2*)&sB[sub * 64 + l * 2];
                }
#pragma unroll
                for (int mi = 0; mi < 4; mi++)
#pragma unroll
                    for (int ni = 0; ni < 4; ni++)
                        mma_tf32(c[mi][ni], a[mi], b[ni]);
            }
        }

        if (it + 1 < NITER) {
            uint32_t* sA = sm + ((it + 1) & 1) * STAGE_U32;
            uint32_t* sB = sA + 4096;
#pragma unroll
            for (int j = 0; j < 4; j++) {
                const float* af = (const float*)&av[j];
                const float* bf = (const float*)&bv[j];
#pragma unroll
                for (int t = 0; t < 4; t++) sA[a_sts[j] + t * 4] = f2tf32(af[t]);
#pragma unroll
                for (int t = 0; t < 4; t++) sB[b_sts[j] + t * 8] = f2tf32(bf[t]);
            }
        }
        __syncthreads();
    }
}

// ---------------------------------------------------------------------------
// QKV projection: grid (8, 32, 3); z selects {Q,K,V}. Writes [B,H,S,D].
// ---------------------------------------------------------------------------
__global__ void __launch_bounds__(256, 1)
qkv_kernel(const float* __restrict__ x,
           const float* __restrict__ Wq, const float* __restrict__ bq,
           const float* __restrict__ Wk, const float* __restrict__ bk,
           const float* __restrict__ Wv, const float* __restrict__ bv)
{
    extern __shared__ uint32_t sm_u32[];

    const float* W;
    const float* bias;
    float* dst;
    if (blockIdx.z == 0)      { W = Wq; bias = bq; dst = g_q; }
    else if (blockIdx.z == 1) { W = Wk; bias = bk; dst = g_k; }
    else                      { W = Wv; bias = bv; dst = g_v; }

    float c[4][4][4];
    gemm_mma_tile(x, W, c, sm_u32);

    const int tid = threadIdx.x;
    const int w = tid >> 5, l = tid & 31;
    const int wm = w >> 2, wn = w & 3;
    const int rbase = blockIdx.y * BM + wm * 64;
    const int cbase = blockIdx.x * BN + wn * 32;

#pragma unroll
    for (int mi = 0; mi < 4; mi++)
#pragma unroll
        for (int ni = 0; ni < 4; ni++) {
            int row0 = rbase + mi * 16 + (l >> 2);
            int col  = cbase + ni * 8 + (l & 3) * 2;
            float b0 = bias[col], b1 = bias[col + 1];
            int h = col >> 6, d = col & 63;
#pragma unroll
            for (int half = 0; half < 2; half++) {
                int row = row0 + half * 8;
                int b = row >> 11, s = row & 2047;
                float2 v;
                v.x = c[mi][ni][half * 2 + 0] + b0;
                v.y = c[mi][ni][half * 2 + 1] + b1;
                *(float2*)(dst + ((size_t)(b * HH + h) * SS + s) * DD + d) = v;
            }
        }
}

// ---------------------------------------------------------------------------
// Output projection: g_attn[4096,1024] @ Wo + bo -> d_out
// ---------------------------------------------------------------------------
__global__ void __launch_bounds__(256, 1)
proj_kernel(const float* __restrict__ Wo, const float* __restrict__ bo,
            float* __restrict__ out)
{
    extern __shared__ uint32_t sm_u32[];

    float c[4][4][4];
    gemm_mma_tile(g_attn, Wo, c, sm_u32);

    const int tid = threadIdx.x;
    const int w = tid >> 5, l = tid & 31;
    const int wm = w >> 2, wn = w & 3;
    const int rbase = blockIdx.y * BM + wm * 64;
    const int cbase = blockIdx.x * BN + wn * 32;

#pragma unroll
    for (int mi = 0; mi < 4; mi++)
#pragma unroll
        for (int ni = 0; ni < 4; ni++) {
            int row0 = rbase + mi * 16 + (l >> 2);
            int col  = cbase + ni * 8 + (l & 3) * 2;
            float b0 = bo[col], b1 = bo[col + 1];
#pragma unroll
            for (int half = 0; half < 2; half++) {
                int row = row0 + half * 8;
                float2 v;
                v.x = c[mi][ni][half * 2 + 0] + b0;
                v.y = c[mi][ni][half * 2 + 1] + b1;
                *(float2*)(out + (size_t)row * EE + col) = v;
            }
        }
}

// ---------------------------------------------------------------------------
// Flash attention, fp32, causal. grid (S/64, B*H), 256 threads. (unchanged)
// ---------------------------------------------------------------------------
#define ATTN_SMEM_FLOATS (4 * 64 * 65 + 3 * 64)

__global__ void __launch_bounds__(256)
attn_kernel()
{
    extern __shared__ float sm[];
    float* Qs    = sm;                 // [64][65]
    float* Ks    = Qs + 64 * 65;
    float* Vs    = Ks + 64 * 65;
    float* Ps    = Vs + 64 * 65;
    float* row_m = Ps + 64 * 65;
    float* row_l = row_m + 64;
    float* row_f = row_l + 64;

    const int tid = threadIdx.x;
    const int tx = tid & 15, ty = tid >> 4;
    const int qt = blockIdx.x;
    const int bh = blockIdx.y;
    const int q0 = qt * 64;

    const float* Qb = g_q + (size_t)bh * SS * DD;
    const float* Kb = g_k + (size_t)bh * SS * DD;
    const float* Vb = g_v + (size_t)bh * SS * DD;

    for (int i = tid; i < 64 * 64; i += 256) {
        int r = i >> 6, c = i & 63;
        Qs[r * 65 + c] = Qb[(q0 + r) * DD + c] * 0.125f;
    }
    if (tid < 64) { row_m[tid] = -1e30f; row_l[tid] = 0.f; }

    float acc[4][4];
#pragma unroll
    for (int i = 0; i < 4; i++)
#pragma unroll
        for (int j = 0; j < 4; j++) acc[i][j] = 0.f;

    for (int jt = 0; jt <= qt; jt++) {
        const int k0 = jt * 64;
        __syncthreads();
        for (int i = tid; i < 64 * 64; i += 256) {
            int r = i >> 6, c = i & 63;
            Ks[r * 65 + c] = Kb[(k0 + r) * DD + c];
            Vs[r * 65 + c] = Vb[(k0 + r) * DD + c];
        }
        __syncthreads();

        float s[4][4];
#pragma unroll
        for (int i = 0; i < 4; i++)
#pragma unroll
            for (int j = 0; j < 4; j++) s[i][j] = 0.f;

#pragma unroll 8
        for (int d = 0; d < 64; d++) {
            float a[4], b[4];
#pragma unroll
            for (int i = 0; i < 4; i++) a[i] = Qs[(ty * 4 + i) * 65 + d];
#pragma unroll
            for (int j = 0; j < 4; j++) b[j] = Ks[(tx * 4 + j) * 65 + d];
#pragma unroll
            for (int i = 0; i < 4; i++)
#pragma unroll
                for (int j = 0; j < 4; j++) s[i][j] += a[i] * b[j];
        }

        if (jt == qt) {
#pragma unroll
            for (int i = 0; i < 4; i++)
#pragma unroll
                for (int j = 0; j < 4; j++)
                    if (tx * 4 + j > ty * 4 + i) s[i][j] = -1e30f;
        }

#pragma unroll
        for (int i = 0; i < 4; i++)
#pragma unroll
            for (int j = 0; j < 4; j++)
                Ps[(ty * 4 + i) * 65 + tx * 4 + j] = s[i][j];
        __syncthreads();

        {
            const int row = tid >> 2;
            const int c0  = (tid & 3) * 16;
            float m = -1e30f;
#pragma unroll
            for (int c = 0; c < 16; c++) m = fmaxf(m, Ps[row * 65 + c0 + c]);
            m = fmaxf(m, __shfl_xor_sync(0xffffffffu, m, 1));
            m = fmaxf(m, __shfl_xor_sync(0xffffffffu, m, 2));
            const float mold = row_m[row];
            const float mnew = fmaxf(mold, m);
            float sum = 0.f;
#pragma unroll
            for (int c = 0; c < 16; c++) {
                float p = __expf(Ps[row * 65 + c0 + c] - mnew);
                Ps[row * 65 + c0 + c] = p;
                sum += p;
            }
            sum += __shfl_xor_sync(0xffffffffu, sum, 1);
            sum += __shfl_xor_sync(0xffffffffu, sum, 2);
            if ((tid & 3) == 0) {
                float f = __expf(mold - mnew);
                row_f[row] = f;
                row_l[row] = row_l[row] * f + sum;
                row_m[row] = mnew;
            }
        }
        __syncthreads();

        float f[4];
#pragma unroll
        for (int i = 0; i < 4; i++) f[i] = row_f[ty * 4 + i];
#pragma unroll
        for (int i = 0; i < 4; i++)
#pragma unroll
            for (int j = 0; j < 4; j++) acc[i][j] *= f[i];

#pragma unroll 8
        for (int kv = 0; kv < 64; kv++) {
            float p[4], v[4];
#pragma unroll
            for (int i = 0; i < 4; i++) p[i] = Ps[(ty * 4 + i) * 65 + kv];
#pragma unroll
            for (int j = 0; j < 4; j++) v[j] = Vs[kv * 65 + tx * 4 + j];
#pragma unroll
            for (int i = 0; i < 4; i++)
#pragma unroll
                for (int j = 0; j < 4; j++) acc[i][j] += p[i] * v[j];
        }
    }
    __syncthreads();

    const int b = bh >> 4;   // H = 16
    const int h = bh & 15;
#pragma unroll
    for (int i = 0; i < 4; i++) {
        const int srow = q0 + ty * 4 + i;
        const float inv = 1.f / row_l[ty * 4 + i];
        float* o = g_attn + ((size_t)(b * SS + srow)) * EE + h * 64 + tx * 4;
#pragma unroll
        for (int j = 0; j < 4; j++) o[j] = acc[i][j] * inv;
    }
}

// ---------------------------------------------------------------------------
// Launch
// ---------------------------------------------------------------------------
extern "C" void kernel_launch(void* const* d_in, const int* in_sizes, int n_in,
                              void* d_out, int out_size)
{
    const float* x  = (const float*)d_in[0];
    const float* Wq = (const float*)d_in[1];
    const float* bq = (const float*)d_in[2];
    const float* Wk = (const float*)d_in[3];
    const float* bk = (const float*)d_in[4];
    const float* Wv = (const float*)d_in[5];
    const float* bv = (const float*)d_in[6];
    const float* Wo = (const float*)d_in[7];
    const float* bo = (const float*)d_in[8];
    float* out = (float*)d_out;

    (void)cudaFuncSetAttribute(qkv_kernel,
                               cudaFuncAttributeMaxDynamicSharedMemorySize,
                               GEMM_SMEM_BYTES);
    (void)cudaFuncSetAttribute(proj_kernel,
                               cudaFuncAttributeMaxDynamicSharedMemorySize,
                               GEMM_SMEM_BYTES);

    // QKV projections: C tiles 128x128 over [4096, 1024], z = {q,k,v}
    dim3 gq(EE / BN, NTOK / BM, 3);
    qkv_kernel<<<gq, 256, GEMM_SMEM_BYTES>>>(x, Wq, bq, Wk, bk, Wv, bv);

    // Flash attention
    const int attn_smem = ATTN_SMEM_FLOATS * (int)sizeof(float);
    (void)cudaFuncSetAttribute(attn_kernel,
                               cudaFuncAttributeMaxDynamicSharedMemorySize,
                               attn_smem);
    dim3 ga(SS / 64, BB * HH);
    attn_kernel<<<ga, 256, attn_smem>>>();

    // Output projection
    dim3 gp(EE / BN, NTOK / BM);
    proj_kernel<<<gp, 256, GEMM_SMEM_BYTES>>>(Wo, bo, out);
}

// round 5
// speedup vs baseline: 3.2637x; 3.2637x over previous
#include <cuda_runtime.h>
#include <math.h>
#include <stdint.h>

// Problem constants
#define BB   2
#define SS   2048
#define EE   1024
#define HH   16
#define DD   64
#define NTOK (BB * SS)   // 4096

// GEMM tiling
#define BM 128
#define BN 128
#define BK 32
#define NITER (EE / BK)          // 32
#define ASTR 36                  // A smem row stride (u32), ≡4 mod 32
#define BSTR 136                 // B smem row stride (u32), ≡8 mod 32
#define STAGE_U32 (BM * ASTR + BK * BSTR)     // 8960
#define GEMM_SMEM_BYTES (2 * STAGE_U32 * 4)   // 71680

// Attention tiling
#define TSTR 68                  // tile row stride (u32), ≡4 mod 32
#define ATTN_SMEM_BYTES (3 * 64 * TSTR * 4)   // 52224

// ---------------------------------------------------------------------------
// Scratch (device globals — no allocation allowed in kernel_launch)
// ---------------------------------------------------------------------------
__device__ float g_q[BB * HH * SS * DD];     // [B,H,S,D]
__device__ float g_k[BB * HH * SS * DD];     // [B,H,S,D]
__device__ float g_v[BB * HH * SS * DD];     // [B,H,D,S]  (TRANSPOSED)
__device__ float g_attn[NTOK * EE];          // [B,S,E]

// ---------------------------------------------------------------------------
// tf32 helpers
// ---------------------------------------------------------------------------
__device__ __forceinline__ uint32_t f2tf32(float f)
{
    uint32_t u;
    asm("cvt.rna.tf32.f32 %0, %1;" : "=r"(u) : "f"(f));
    return u;
}

__device__ __forceinline__ uint4 pack_tf32(float4 v)
{
    uint4 u;
    u.x = f2tf32(v.x); u.y = f2tf32(v.y); u.z = f2tf32(v.z); u.w = f2tf32(v.w);
    return u;
}

__device__ __forceinline__ void mma_tf32(float c[4], const uint32_t a[4],
                                         const uint32_t b[2])
{
    asm volatile(
        "mma.sync.aligned.m16n8k8.row.col.f32.tf32.tf32.f32 "
        "{%0,%1,%2,%3}, {%4,%5,%6,%7}, {%8,%9}, {%0,%1,%2,%3};"
        : "+f"(c[0]), "+f"(c[1]), "+f"(c[2]), "+f"(c[3])
        : "r"(a[0]), "r"(a[1]), "r"(a[2]), "r"(a[3]), "r"(b[0]), "r"(b[1]));
}

// ---------------------------------------------------------------------------
// tf32 MMA GEMM core: one 128x128 tile of A[4096,1024] @ W[1024,1024].
// 256 threads = 8 warps (2x4), warp tile 64x32.
// Plain row-major smem with padded strides (conflict-free STS.128 + LDS.32).
// Double-buffered, register-staged LDG, one barrier per k-iter.
// ---------------------------------------------------------------------------
__device__ __forceinline__ void gemm_mma_tile(const float* __restrict__ A,
                                              const float* __restrict__ W,
                                              float c[4][4][4],
                                              uint32_t* sm)
{
    const int tid = threadIdx.x;
    const int brow = blockIdx.y * BM;
    const int bcol = blockIdx.x * BN;
    const int w = tid >> 5, l = tid & 31;
    const int wm = w >> 2, wn = w & 3;
    const int lg = l >> 2, lt = l & 3;

    // gmem->smem mapping: 4 A float4 + 4 B float4 per thread per iter
    const float* a_ptr[4];
    const float* b_ptr[4];
    int a_sts[4], b_sts[4];
#pragma unroll
    for (int j = 0; j < 4; j++) {
        int p = tid + 256 * j;
        {   // A: 128 rows x 8 float4
            int row = p >> 3, col = (p & 7) * 4;
            a_ptr[j] = A + (size_t)(brow + row) * EE + col;
            a_sts[j] = row * ASTR + col;
        }
        {   // B: 32 rows x 32 float4
            int krow = p >> 5, n = (p & 31) * 4;
            b_ptr[j] = W + (size_t)krow * EE + bcol + n;
            b_sts[j] = BM * ASTR + krow * BSTR + n;
        }
    }

#pragma unroll
    for (int mi = 0; mi < 4; mi++)
#pragma unroll
        for (int ni = 0; ni < 4; ni++)
#pragma unroll
            for (int r = 0; r < 4; r++) c[mi][ni][r] = 0.f;

    float4 av[4], bv[4];
#pragma unroll
    for (int j = 0; j < 4; j++) {
        av[j] = *(const float4*)(a_ptr[j]);
        bv[j] = *(const float4*)(b_ptr[j]);
    }
#pragma unroll
    for (int j = 0; j < 4; j++) {
        *(uint4*)&sm[a_sts[j]] = pack_tf32(av[j]);
        *(uint4*)&sm[b_sts[j]] = pack_tf32(bv[j]);
    }
    __syncthreads();

    for (int it = 0; it < NITER; it++) {
        if (it + 1 < NITER) {
#pragma unroll
            for (int j = 0; j < 4; j++) {
                av[j] = *(const float4*)(a_ptr[j] + (it + 1) * BK);
                bv[j] = *(const float4*)(b_ptr[j] + (size_t)(it + 1) * BK * EE);
            }
        }

        {   // compute on current stage
            const uint32_t* sA = sm + (it & 1) * STAGE_U32;
            const uint32_t* sB = sA + BM * ASTR;
#pragma unroll
            for (int ks = 0; ks < 4; ks++) {
                uint32_t a[4][4], b[4][2];
#pragma unroll
                for (int mi = 0; mi < 4; mi++) {
                    const uint32_t* p = sA + (wm * 64 + mi * 16 + lg) * ASTR
                                           + ks * 8 + lt;
                    a[mi][0] = p[0];
                    a[mi][1] = p[8 * ASTR];
                    a[mi][2] = p[4];
                    a[mi][3] = p[8 * ASTR + 4];
                }
#pragma unroll
                for (int ni = 0; ni < 4; ni++) {
                    const uint32_t* p = sB + (ks * 8 + lt) * BSTR
                                           + wn * 32 + ni * 8 + lg;
                    b[ni][0] = p[0];
                    b[ni][1] = p[4 * BSTR];
                }
#pragma unroll
                for (int mi = 0; mi < 4; mi++)
#pragma unroll
                    for (int ni = 0; ni < 4; ni++)
                        mma_tf32(c[mi][ni], a[mi], b[ni]);
            }
        }

        if (it + 1 < NITER) {
            uint32_t* dst = sm + ((it + 1) & 1) * STAGE_U32;
#pragma unroll
            for (int j = 0; j < 4; j++) {
                *(uint4*)&dst[a_sts[j]] = pack_tf32(av[j]);
                *(uint4*)&dst[b_sts[j]] = pack_tf32(bv[j]);
            }
        }
        __syncthreads();
    }
}

// ---------------------------------------------------------------------------
// QKV projection: grid (8, 32, 3); z selects {Q,K,V}.
// Q,K written [B,H,S,D]; V written TRANSPOSED [B,H,D,S].
// ---------------------------------------------------------------------------
__global__ void __launch_bounds__(256, 1)
qkv_kernel(const float* __restrict__ x,
           const float* __restrict__ Wq, const float* __restrict__ bq,
           const float* __restrict__ Wk, const float* __restrict__ bk,
           const float* __restrict__ Wv, const float* __restrict__ bv)
{
    extern __shared__ uint32_t sm_u32[];

    const float* W;
    const float* bias;
    if (blockIdx.z == 0)      { W = Wq; bias = bq; }
    else if (blockIdx.z == 1) { W = Wk; bias = bk; }
    else                      { W = Wv; bias = bv; }

    float c[4][4][4];
    gemm_mma_tile(x, W, c, sm_u32);

    const int tid = threadIdx.x;
    const int w = tid >> 5, l = tid & 31;
    const int wm = w >> 2, wn = w & 3;
    const int rbase = blockIdx.y * BM + wm * 64;
    const int cbase = blockIdx.x * BN + wn * 32;

    if (blockIdx.z < 2) {
        float* dst = (blockIdx.z == 0) ? g_q : g_k;
#pragma unroll
        for (int mi = 0; mi < 4; mi++)
#pragma unroll
            for (int ni = 0; ni < 4; ni++) {
                int row0 = rbase + mi * 16 + (l >> 2);
                int col  = cbase + ni * 8 + (l & 3) * 2;
                float b0 = bias[col], b1 = bias[col + 1];
                int h = col >> 6, d = col & 63;
#pragma unroll
                for (int half = 0; half < 2; half++) {
                    int t = row0 + half * 8;
                    int b = t >> 11, s = t & 2047;
                    float2 v;
                    v.x = c[mi][ni][half * 2 + 0] + b0;
                    v.y = c[mi][ni][half * 2 + 1] + b1;
                    *(float2*)(dst + ((size_t)(b * HH + h) * SS + s) * DD + d) = v;
                }
            }
    } else {
        // V transposed: [B,H,D,S]
#pragma unroll
        for (int mi = 0; mi < 4; mi++)
#pragma unroll
            for (int ni = 0; ni < 4; ni++) {
                int row0 = rbase + mi * 16 + (l >> 2);
                int col  = cbase + ni * 8 + (l & 3) * 2;
                float b0 = bias[col], b1 = bias[col + 1];
                int h = col >> 6, d = col & 63;
#pragma unroll
                for (int half = 0; half < 2; half++) {
                    int t = row0 + half * 8;
                    int b = t >> 11, s = t & 2047;
                    size_t base = ((size_t)(b * HH + h) * DD);
                    g_v[(base + d)     * SS + s] = c[mi][ni][half * 2 + 0] + b0;
                    g_v[(base + d + 1) * SS + s] = c[mi][ni][half * 2 + 1] + b1;
                }
            }
    }
}

// ---------------------------------------------------------------------------
// Output projection: g_attn[4096,1024] @ Wo + bo -> d_out
// ---------------------------------------------------------------------------
__global__ void __launch_bounds__(256, 1)
proj_kernel(const float* __restrict__ Wo, const float* __restrict__ bo,
            float* __restrict__ out)
{
    extern __shared__ uint32_t sm_u32[];

    float c[4][4][4];
    gemm_mma_tile(g_attn, Wo, c, sm_u32);

    const int tid = threadIdx.x;
    const int w = tid >> 5, l = tid & 31;
    const int wm = w >> 2, wn = w & 3;
    const int rbase = blockIdx.y * BM + wm * 64;
    const int cbase = blockIdx.x * BN + wn * 32;

#pragma unroll
    for (int mi = 0; mi < 4; mi++)
#pragma unroll
        for (int ni = 0; ni < 4; ni++) {
            int row0 = rbase + mi * 16 + (l >> 2);
            int col  = cbase + ni * 8 + (l & 3) * 2;
            float b0 = bo[col], b1 = bo[col + 1];
#pragma unroll
            for (int half = 0; half < 2; half++) {
                int row = row0 + half * 8;
                float2 v;
                v.x = c[mi][ni][half * 2 + 0] + b0;
                v.y = c[mi][ni][half * 2 + 1] + b1;
                *(float2*)(out + (size_t)row * EE + col) = v;
            }
        }
}

// ---------------------------------------------------------------------------
// Flash attention, tf32 MMA, causal. grid (32, 32): x -> qt (reversed), y -> bh.
// 128 threads = 4 warps; warp w owns q-rows [w*16, w*16+16).
// Smem: Qs(->Ps reuse) / Ks / Vs, each [64][TSTR] u32.
// ---------------------------------------------------------------------------
__global__ void __launch_bounds__(128, 3)
attn_kernel()
{
    extern __shared__ uint32_t smu[];
    uint32_t* Qs = smu;               // later reused as Ps
    uint32_t* Ks = smu + 64 * TSTR;
    uint32_t* Vs = smu + 2 * 64 * TSTR;

    const int tid = threadIdx.x;
    const int w = tid >> 5, l = tid & 31;
    const int lg = l >> 2, lt = l & 3;
    const int qt = (gridDim.x - 1) - blockIdx.x;
    const int bh = blockIdx.y;
    const int q0 = qt * 64;

    const float* Qg = g_q + (size_t)bh * SS * DD;
    const float* Kg = g_k + (size_t)bh * SS * DD;
    const float* Vg = g_v + (size_t)bh * DD * SS;   // [D,S]

    // ---- load Q tile (scaled) into smem, tf32 ----
#pragma unroll
    for (int j = 0; j < 8; j++) {
        int p = tid + 128 * j;
        int r = p >> 4, cc = (p & 15) * 4;
        float4 v = *(const float4*)(Qg + (size_t)(q0 + r) * DD + cc);
        v.x *= 0.125f; v.y *= 0.125f; v.z *= 0.125f; v.w *= 0.125f;
        *(uint4*)&Qs[r * TSTR + cc] = pack_tf32(v);
    }
    __syncthreads();

    // ---- hoist Q A-fragments into registers (whole KV loop) ----
    uint32_t qa[8][4];
#pragma unroll
    for (int ks = 0; ks < 8; ks++) {
        const uint32_t* p = Qs + (w * 16 + lg) * TSTR + ks * 8 + lt;
        qa[ks][0] = p[0];
        qa[ks][1] = p[8 * TSTR];
        qa[ks][2] = p[4];
        qa[ks][3] = p[8 * TSTR + 4];
    }
    __syncthreads();   // all warps done reading Qs before it becomes Ps
    uint32_t* Ps = Qs;

    float m_i[2] = { -1e30f, -1e30f };
    float l_i[2] = { 0.f, 0.f };
    float oacc[8][4];
#pragma unroll
    for (int ni = 0; ni < 8; ni++)
#pragma unroll
        for (int r = 0; r < 4; r++) oacc[ni][r] = 0.f;

    for (int jt = 0; jt <= qt; jt++) {
        const int k0 = jt * 64;
        __syncthreads();   // prev iter done with Ks/Vs (and Ps reads)
#pragma unroll
        for (int j = 0; j < 8; j++) {
            int p = tid + 128 * j;
            int r = p >> 4, cc = (p & 15) * 4;
            float4 kv4 = *(const float4*)(Kg + (size_t)(k0 + r) * DD + cc);
            *(uint4*)&Ks[r * TSTR + cc] = pack_tf32(kv4);
            float4 vv4 = *(const float4*)(Vg + (size_t)r * SS + k0 + cc);
            *(uint4*)&Vs[r * TSTR + cc] = pack_tf32(vv4);
        }
        __syncthreads();

        // ---- S = Q @ K^T (warp rows x 64 kv) ----
        float sc[8][4];
#pragma unroll
        for (int ni = 0; ni < 8; ni++)
#pragma unroll
            for (int r = 0; r < 4; r++) sc[ni][r] = 0.f;

#pragma unroll
        for (int ks = 0; ks < 8; ks++) {
#pragma unroll
            for (int ni = 0; ni < 8; ni++) {
                const uint32_t* p = Ks + (ni * 8 + lg) * TSTR + ks * 8 + lt;
                uint32_t b[2] = { p[0], p[4] };
                mma_tf32(sc[ni], qa[ks], b);
            }
        }

        // ---- causal mask on diagonal tile ----
        if (jt == qt) {
#pragma unroll
            for (int ni = 0; ni < 8; ni++)
#pragma unroll
                for (int r = 0; r < 4; r++) {
                    int row = w * 16 + lg + (r >> 1) * 8;
                    int col = ni * 8 + lt * 2 + (r & 1);
                    if (col > row) sc[ni][r] = -1e30f;
                }
        }

        // ---- online softmax (registers + 4-lane shuffles) ----
#pragma unroll
        for (int rh = 0; rh < 2; rh++) {
            float m = -1e30f;
#pragma unroll
            for (int ni = 0; ni < 8; ni++) {
                m = fmaxf(m, sc[ni][rh * 2]);
                m = fmaxf(m, sc[ni][rh * 2 + 1]);
            }
            m = fmaxf(m, __shfl_xor_sync(0xffffffffu, m, 1));
            m = fmaxf(m, __shfl_xor_sync(0xffffffffu, m, 2));
            float mnew = fmaxf(m_i[rh], m);
            float f = __expf(m_i[rh] - mnew);
            float sum = 0.f;
#pragma unroll
            for (int ni = 0; ni < 8; ni++) {
                float p0 = __expf(sc[ni][rh * 2]     - mnew);
                float p1 = __expf(sc[ni][rh * 2 + 1] - mnew);
                sc[ni][rh * 2]     = p0;
                sc[ni][rh * 2 + 1] = p1;
                sum += p0 + p1;
            }
            sum += __shfl_xor_sync(0xffffffffu, sum, 1);
            sum += __shfl_xor_sync(0xffffffffu, sum, 2);
            l_i[rh] = l_i[rh] * f + sum;
            m_i[rh] = mnew;
#pragma unroll
            for (int ni = 0; ni < 8; ni++) {
                oacc[ni][rh * 2]     *= f;
                oacc[ni][rh * 2 + 1] *= f;
            }
        }

        // ---- write P to smem (warp-private rows) ----
#pragma unroll
        for (int ni = 0; ni < 8; ni++)
#pragma unroll
            for (int rh = 0; rh < 2; rh++) {
                uint2 pv;
                pv.x = f2tf32(sc[ni][rh * 2]);
                pv.y = f2tf32(sc[ni][rh * 2 + 1]);
                *(uint2*)&Ps[(w * 16 + lg + rh * 8) * TSTR + ni * 8 + lt * 2] = pv;
            }
        __syncwarp();

        // ---- O += P @ V ----
#pragma unroll
        for (int ks = 0; ks < 8; ks++) {
            uint32_t pa[4];
            const uint32_t* pp = Ps + (w * 16 + lg) * TSTR + ks * 8 + lt;
            pa[0] = pp[0];
            pa[1] = pp[8 * TSTR];
            pa[2] = pp[4];
            pa[3] = pp[8 * TSTR + 4];
#pragma unroll
            for (int ni = 0; ni < 8; ni++) {
                const uint32_t* p = Vs + (ni * 8 + lg) * TSTR + ks * 8 + lt;
                uint32_t b[2] = { p[0], p[4] };
                mma_tf32(oacc[ni], pa, b);
            }
        }
        __syncwarp();   // P reads done before next-iter (cross-warp via top sync)
    }

    // ---- epilogue: normalize, write [B,S,E] ----
    const int b = bh >> 4;
    const int h = bh & 15;
    float inv[2] = { 1.f / l_i[0], 1.f / l_i[1] };
#pragma unroll
    for (int ni = 0; ni < 8; ni++)
#pragma unroll
        for (int rh = 0; rh < 2; rh++) {
            int s = q0 + w * 16 + lg + rh * 8;
            int e = h * 64 + ni * 8 + lt * 2;
            float2 v;
            v.x = oacc[ni][rh * 2]     * inv[rh];
            v.y = oacc[ni][rh * 2 + 1] * inv[rh];
            *(float2*)(g_attn + (size_t)(b * SS + s) * EE + e) = v;
        }
}

// ---------------------------------------------------------------------------
// Launch
// ---------------------------------------------------------------------------
extern "C" void kernel_launch(void* const* d_in, const int* in_sizes, int n_in,
                              void* d_out, int out_size)
{
    const float* x  = (const float*)d_in[0];
    const float* Wq = (const float*)d_in[1];
    const float* bq = (const float*)d_in[2];
    const float* Wk = (const float*)d_in[3];
    const float* bk = (const float*)d_in[4];
    const float* Wv = (const float*)d_in[5];
    const float* bv = (const float*)d_in[6];
    const float* Wo = (const float*)d_in[7];
    const float* bo = (const float*)d_in[8];
    float* out = (float*)d_out;

    (void)cudaFuncSetAttribute(qkv_kernel,
                               cudaFuncAttributeMaxDynamicSharedMemorySize,
                               GEMM_SMEM_BYTES);
    (void)cudaFuncSetAttribute(proj_kernel,
                               cudaFuncAttributeMaxDynamicSharedMemorySize,
                               GEMM_SMEM_BYTES);
    (void)cudaFuncSetAttribute(attn_kernel,
                               cudaFuncAttributeMaxDynamicSharedMemorySize,
                               ATTN_SMEM_BYTES);

    dim3 gq(EE / BN, NTOK / BM, 3);
    qkv_kernel<<<gq, 256, GEMM_SMEM_BYTES>>>(x, Wq, bq, Wk, bk, Wv, bv);

    dim3 ga(SS / 64, BB * HH);
    attn_kernel<<<ga, 128, ATTN_SMEM_BYTES>>>();

    dim3 gp(EE / BN, NTOK / BM);
    proj_kernel<<<gp, 256, GEMM_SMEM_BYTES>>>(Wo, bo, out);
}

// round 7
// speedup vs baseline: 3.9431x; 1.2082x over previous
#include <cuda_runtime.h>
#include <math.h>
#include <stdint.h>

// Problem constants
#define BB   2
#define SS   2048
#define EE   1024
#define HH   16
#define DD   64
#define NTOK (BB * SS)   // 4096

// GEMM tiling: CTA 128x256xk32, 8 warps, warp tile 64x64
#define GBM 128
#define GBN 256
#define GBK 32
#define GNIT (EE / GBK)                 // 32
#define NSTG 3
#define A_BYTES (GBM * 128)             // 16384 (128 rows x 128B)
#define B_BYTES (GBN * 128)             // 32768 (256 rows x 128B)
#define STG_BYTES (A_BYTES + B_BYTES)   // 49152
#define GEMM_SMEM (NSTG * STG_BYTES)    // 147456

// Attention tiling
#define TSTR 68
#define ATTN_SMEM_BYTES (3 * 64 * TSTR * 4)   // 52224

// ---------------------------------------------------------------------------
// Scratch
// ---------------------------------------------------------------------------
__device__ float g_x[NTOK * EE];             // x, tf32-rounded
__device__ float g_wt[4 * EE * EE];          // Wq^T,Wk^T,Wv^T,Wo^T, rounded
__device__ float g_q[BB * HH * SS * DD];     // [B,H,S,D]
__device__ float g_k[BB * HH * SS * DD];     // [B,H,S,D]
__device__ float g_v[BB * HH * SS * DD];     // [B,H,D,S] (transposed)
__device__ float g_attn[NTOK * EE];          // [B,S,E], tf32-rounded

// ---------------------------------------------------------------------------
// helpers
// ---------------------------------------------------------------------------
__device__ __forceinline__ uint32_t f2tf32(float f)
{
    uint32_t u;
    asm("cvt.rna.tf32.f32 %0, %1;" : "=r"(u) : "f"(f));
    return u;
}

__device__ __forceinline__ uint4 pack_tf32(float4 v)
{
    uint4 u;
    u.x = f2tf32(v.x); u.y = f2tf32(v.y); u.z = f2tf32(v.z); u.w = f2tf32(v.w);
    return u;
}

__device__ __forceinline__ void mma_tf32(float c[4], const uint32_t a[4],
                                         const uint32_t b[2])
{
    asm volatile(
        "mma.sync.aligned.m16n8k8.row.col.f32.tf32.tf32.f32 "
        "{%0,%1,%2,%3}, {%4,%5,%6,%7}, {%8,%9}, {%0,%1,%2,%3};"
        : "+f"(c[0]), "+f"(c[1]), "+f"(c[2]), "+f"(c[3])
        : "r"(a[0]), "r"(a[1]), "r"(a[2]), "r"(a[3]), "r"(b[0]), "r"(b[1]));
}

__device__ __forceinline__ uint32_t s2u(const void* p)
{
    return (uint32_t)__cvta_generic_to_shared(p);
}

__device__ __forceinline__ void cpa16(uint32_t dst, const void* src)
{
    asm volatile("cp.async.cg.shared.global [%0], [%1], 16;"
                 :: "r"(dst), "l"(src) : "memory");
}
__device__ __forceinline__ void cpa_commit()
{
    asm volatile("cp.async.commit_group;" ::: "memory");
}
__device__ __forceinline__ void cpa_wait1()
{
    asm volatile("cp.async.wait_group 1;" ::: "memory");
}

__device__ __forceinline__ void ldsm4(uint32_t* r, uint32_t a)
{
    asm volatile("ldmatrix.sync.aligned.m8n8.x4.shared.b16 {%0,%1,%2,%3}, [%4];"
                 : "=r"(r[0]), "=r"(r[1]), "=r"(r[2]), "=r"(r[3]) : "r"(a));
}

// fast 2^x on the FMA pipe (x <= 0; Taylor deg-4, rel err ~4e-5)
__device__ __forceinline__ float fexp2(float x)
{
    x = fmaxf(x, -100.f);
    float z = x + 12582912.f;           // round-to-nearest capture
    float f = x - (z - 12582912.f);     // f in [-0.5, 0.5]
    float p = fmaf(f, 0.009618129f, 0.055504109f);
    p = fmaf(f, p, 0.240226507f);
    p = fmaf(f, p, 0.693147181f);
    p = fmaf(f, p, 1.0f);
    int e = (int)((unsigned)__float_as_int(z) << 23);
    return __int_as_float(__float_as_int(p) + e);
}

// ---------------------------------------------------------------------------
// Pre-pass: round x -> g_x (tf32 values stored as f32)
// ---------------------------------------------------------------------------
__global__ void __launch_bounds__(256)
prep_x(const float* __restrict__ x)
{
    const int i = blockIdx.x * 256 + threadIdx.x;   // grid 1024 -> 262144 thr
#pragma unroll
    for (int j = 0; j < 4; j++) {
        int idx = i + j * 262144;                   // float4 index, < 1M
        float4 v = ((const float4*)x)[idx];
        uint4 u = pack_tf32(v);
        float4 o;
        o.x = __uint_as_float(u.x); o.y = __uint_as_float(u.y);
        o.z = __uint_as_float(u.z); o.w = __uint_as_float(u.w);
        ((float4*)g_x)[idx] = o;
    }
}

// ---------------------------------------------------------------------------
// Pre-pass: transpose + round W -> g_wt  (Wt[n][k] = round(W[k][n]))
// grid (32, 32, 4), 256 threads, 32x32 tiles
// ---------------------------------------------------------------------------
__global__ void __launch_bounds__(256)
prep_w(const float* __restrict__ Wq, const float* __restrict__ Wk,
       const float* __restrict__ Wv, const float* __restrict__ Wo)
{
    __shared__ float t[32][33];
    const float* W;
    if (blockIdx.z == 0)      W = Wq;
    else if (blockIdx.z == 1) W = Wk;
    else if (blockIdx.z == 2) W = Wv;
    else                      W = Wo;
    float* out = g_wt + (size_t)blockIdx.z * EE * EE;

    const int n0 = blockIdx.x * 32, k0 = blockIdx.y * 32;
    const int x = threadIdx.x & 31, y = threadIdx.x >> 5;
#pragma unroll
    for (int i = 0; i < 4; i++)
        t[y + 8 * i][x] = W[(size_t)(k0 + y + 8 * i) * EE + n0 + x];
    __syncthreads();
#pragma unroll
    for (int i = 0; i < 4; i++)
        out[(size_t)(n0 + y + 8 * i) * EE + k0 + x] =
            __uint_as_float(f2tf32(t[x][y + 8 * i]));
}

// ---------------------------------------------------------------------------
// GEMM core: C[128x256] tile of A[.,1024] @ Bt^T (Bt is [n][k]).
// All-cp.async 3-stage pipeline, XOR-swizzled smem, ldmatrix fragments.
// A and Bt must be tf32-pre-rounded.
// ---------------------------------------------------------------------------
__device__ __forceinline__ void gemm_core(const float* __restrict__ A,
                                          const float* __restrict__ Bt,
                                          int brow, int bcol,
                                          float c[4][8][4], char* sm)
{
    const int tid = threadIdx.x;
    const int w = tid >> 5, l = tid & 31;
    const int wm = w >> 2, wn = w & 3;
    const uint32_t sb = s2u(sm);

    // cp.async mappings (16B chunks)
    const float* asrc[4]; uint32_t adst[4];
#pragma unroll
    for (int j = 0; j < 4; j++) {
        int idx = tid + 256 * j;                 // A: 128 rows x 8 chunks
        int row = idx >> 3, kc = idx & 7;
        asrc[j] = A + (size_t)(brow + row) * EE + kc * 4;
        adst[j] = row * 128 + ((kc ^ (row & 7)) << 4);
    }
    const float* bsrc[8]; uint32_t bdst[8];
#pragma unroll
    for (int j = 0; j < 8; j++) {
        int idx = tid + 256 * j;                 // B: 256 rows x 8 chunks
        int n = idx >> 3, kc = idx & 7;
        bsrc[j] = Bt + (size_t)(bcol + n) * EE + kc * 4;
        bdst[j] = A_BYTES + n * 128 + ((kc ^ (n & 7)) << 4);
    }

#pragma unroll
    for (int mi = 0; mi < 4; mi++)
#pragma unroll
        for (int ni = 0; ni < 8; ni++)
#pragma unroll
            for (int r = 0; r < 4; r++) c[mi][ni][r] = 0.f;

    // prologue: stages 0,1
#pragma unroll
    for (int s = 0; s < 2; s++) {
        uint32_t so = sb + s * STG_BYTES;
        int k0 = s * GBK;
#pragma unroll
        for (int j = 0; j < 4; j++) cpa16(so + adst[j], asrc[j] + k0);
#pragma unroll
        for (int j = 0; j < 8; j++) cpa16(so + bdst[j], bsrc[j] + k0);
        cpa_commit();
    }

    // ldmatrix per-lane address components
    const uint32_t abase = (uint32_t)((wm * 64 + (l & 15)) * 128);
    const int ahalf = l >> 4;
    const int axor = l & 7;
    const uint32_t bbase = (uint32_t)(A_BYTES +
                          (wn * 64 + (l & 7) + ((l >> 4) << 3)) * 128);
    const int bhalf = (l >> 3) & 1;
    const int bxor = l & 7;

    int stage = 0;
    for (int it = 0; it < GNIT; it++) {
        cpa_wait1();
        __syncthreads();

        if (it + 2 < GNIT) {
            int ls = (stage + 2) % NSTG;
            uint32_t so = sb + ls * STG_BYTES;
            int k0 = (it + 2) * GBK;
#pragma unroll
            for (int j = 0; j < 4; j++) cpa16(so + adst[j], asrc[j] + k0);
#pragma unroll
            for (int j = 0; j < 8; j++) cpa16(so + bdst[j], bsrc[j] + k0);
        }
        cpa_commit();

        const uint32_t so = sb + stage * STG_BYTES;
#pragma unroll
        for (int ks = 0; ks < 4; ks++) {
            uint32_t af[4][4], bf[4][4];
#pragma unroll
            for (int mi = 0; mi < 4; mi++)
                ldsm4(af[mi], so + abase + mi * 2048 +
                      ((uint32_t)((2 * ks + ahalf) ^ axor) << 4));
#pragma unroll
            for (int n2 = 0; n2 < 4; n2++)
                ldsm4(bf[n2], so + bbase + n2 * 2048 +
                      ((uint32_t)((2 * ks + bhalf) ^ bxor) << 4));
#pragma unroll
            for (int mi = 0; mi < 4; mi++)
#pragma unroll
                for (int n2 = 0; n2 < 4; n2++) {
                    mma_tf32(c[mi][2 * n2],     af[mi], &bf[n2][0]);
                    mma_tf32(c[mi][2 * n2 + 1], af[mi], &bf[n2][2]);
                }
        }
        stage = (stage + 1) % NSTG;
    }
}

// ---------------------------------------------------------------------------
// QKV: grid (4, 32, 3); z selects {Q,K,V}. Q,K -> [B,H,S,D]; V -> [B,H,D,S].
// ---------------------------------------------------------------------------
__global__ void __launch_bounds__(256, 1)
qkv_mma(const float* __restrict__ bq, const float* __restrict__ bk,
        const float* __restrict__ bv)
{
    extern __shared__ char smc[];
    const float* bias;
    if (blockIdx.z == 0)      bias = bq;
    else if (blockIdx.z == 1) bias = bk;
    else                      bias = bv;
    const float* Bt = g_wt + (size_t)blockIdx.z * EE * EE;

    const int brow = blockIdx.y * GBM;
    const int bcol = blockIdx.x * GBN;

    float c[4][8][4];
    gemm_core(g_x, Bt, brow, bcol, c, smc);

    const int tid = threadIdx.x;
    const int w = tid >> 5, l = tid & 31;
    const int wm = w >> 2, wn = w & 3;

#pragma unroll
    for (int mi = 0; mi < 4; mi++)
#pragma unroll
        for (int ni = 0; ni < 8; ni++) {
            int row0 = brow + wm * 64 + mi * 16 + (l >> 2);
            int col  = bcol + wn * 64 + ni * 8 + (l & 3) * 2;
            float b0 = bias[col], b1 = bias[col + 1];
            int h = col >> 6, d = col & 63;
#pragma unroll
            for (int half = 0; half < 2; half++) {
                int t = row0 + half * 8;
                int b = t >> 11, s = t & 2047;
                float v0 = c[mi][ni][half * 2 + 0] + b0;
                float v1 = c[mi][ni][half * 2 + 1] + b1;
                if (blockIdx.z < 2) {
                    float* dst = (blockIdx.z == 0) ? g_q : g_k;
                    float2 v; v.x = v0; v.y = v1;
                    *(float2*)(dst + ((size_t)(b * HH + h) * SS + s) * DD + d) = v;
                } else {
                    size_t base = (size_t)(b * HH + h) * DD;
                    g_v[(base + d)     * SS + s] = v0;
                    g_v[(base + d + 1) * SS + s] = v1;
                }
            }
        }
}

// ---------------------------------------------------------------------------
// Out-proj: grid (4, 32). g_attn @ Wo + bo -> out.
// ---------------------------------------------------------------------------
__global__ void __launch_bounds__(256, 1)
proj_mma(const float* __restrict__ bo, float* __restrict__ out)
{
    extern __shared__ char smc[];
    const float* Bt = g_wt + (size_t)3 * EE * EE;

    const int brow = blockIdx.y * GBM;
    const int bcol = blockIdx.x * GBN;

    float c[4][8][4];
    gemm_core(g_attn, Bt, brow, bcol, c, smc);

    const int tid = threadIdx.x;
    const int w = tid >> 5, l = tid & 31;
    const int wm = w >> 2, wn = w & 3;

#pragma unroll
    for (int mi = 0; mi < 4; mi++)
#pragma unroll
        for (int ni = 0; ni < 8; ni++) {
            int row0 = brow + wm * 64 + mi * 16 + (l >> 2);
            int col  = bcol + wn * 64 + ni * 8 + (l & 3) * 2;
            float b0 = bo[col], b1 = bo[col + 1];
#pragma unroll
            for (int half = 0; half < 2; half++) {
                int row = row0 + half * 8;
                float2 v;
                v.x = c[mi][ni][half * 2 + 0] + b0;
                v.y = c[mi][ni][half * 2 + 1] + b1;
                *(float2*)(out + (size_t)row * EE + col) = v;
            }
        }
}

// ---------------------------------------------------------------------------
// Flash attention, tf32 mma.sync, causal, base-2 softmax with hybrid exp.
// grid (32, 32): x -> qt (reversed), y -> bh. 128 threads = 4 warps.
// ---------------------------------------------------------------------------
__global__ void __launch_bounds__(128, 3)
attn_kernel()
{
    extern __shared__ uint32_t smu[];
    uint32_t* Qs = smu;               // later reused as Ps
    uint32_t* Ks = smu + 64 * TSTR;
    uint32_t* Vs = smu + 2 * 64 * TSTR;

    const int tid = threadIdx.x;
    const int w = tid >> 5, l = tid & 31;
    const int lg = l >> 2, lt = l & 3;
    const int qt = (gridDim.x - 1) - blockIdx.x;
    const int bh = blockIdx.y;
    const int q0 = qt * 64;

    const float* Qg = g_q + (size_t)bh * SS * DD;
    const float* Kg = g_k + (size_t)bh * SS * DD;
    const float* Vg = g_v + (size_t)bh * DD * SS;   // [D,S]

    // Q scale folds 1/sqrt(D) AND log2(e) -> softmax in base 2
    const float qscale = 0.125f * 1.44269504f;
#pragma unroll
    for (int j = 0; j < 8; j++) {
        int p = tid + 128 * j;
        int r = p >> 4, cc = (p & 15) * 4;
        float4 v = *(const float4*)(Qg + (size_t)(q0 + r) * DD + cc);
        v.x *= qscale; v.y *= qscale; v.z *= qscale; v.w *= qscale;
        *(uint4*)&Qs[r * TSTR + cc] = pack_tf32(v);
    }
    __syncthreads();

    uint32_t qa[8][4];
#pragma unroll
    for (int ks = 0; ks < 8; ks++) {
        const uint32_t* p = Qs + (w * 16 + lg) * TSTR + ks * 8 + lt;
        qa[ks][0] = p[0];
        qa[ks][1] = p[8 * TSTR];
        qa[ks][2] = p[4];
        qa[ks][3] = p[8 * TSTR + 4];
    }
    __syncthreads();
    uint32_t* Ps = Qs;

    float m_i[2] = { -1e30f, -1e30f };
    float l_i[2] = { 0.f, 0.f };
    float oacc[8][4];
#pragma unroll
    for (int ni = 0; ni < 8; ni++)
#pragma unroll
        for (int r = 0; r < 4; r++) oacc[ni][r] = 0.f;

    for (int jt = 0; jt <= qt; jt++) {
        const int k0 = jt * 64;
        __syncthreads();
#pragma unroll
        for (int j = 0; j < 8; j++) {
            int p = tid + 128 * j;
            int r = p >> 4, cc = (p & 15) * 4;
            float4 kv4 = *(const float4*)(Kg + (size_t)(k0 + r) * DD + cc);
            *(uint4*)&Ks[r * TSTR + cc] = pack_tf32(kv4);
            float4 vv4 = *(const float4*)(Vg + (size_t)r * SS + k0 + cc);
            *(uint4*)&Vs[r * TSTR + cc] = pack_tf32(vv4);
        }
        __syncthreads();

        float sc[8][4];
#pragma unroll
        for (int ni = 0; ni < 8; ni++)
#pragma unroll
            for (int r = 0; r < 4; r++) sc[ni][r] = 0.f;

#pragma unroll
        for (int ks = 0; ks < 8; ks++) {
#pragma unroll
            for (int ni = 0; ni < 8; ni++) {
                const uint32_t* p = Ks + (ni * 8 + lg) * TSTR + ks * 8 + lt;
                uint32_t b[2] = { p[0], p[4] };
                mma_tf32(sc[ni], qa[ks], b);
            }
        }

        if (jt == qt) {
#pragma unroll
            for (int ni = 0; ni < 8; ni++)
#pragma unroll
                for (int r = 0; r < 4; r++) {
                    int row = w * 16 + lg + (r >> 1) * 8;
                    int col = ni * 8 + lt * 2 + (r & 1);
                    if (col > row) sc[ni][r] = -1e30f;
                }
        }

        // online softmax (base 2); ni 0..5 via MUFU exp2f, ni 6..7 via FMA poly
#pragma unroll
        for (int rh = 0; rh < 2; rh++) {
            float m = -1e30f;
#pragma unroll
            for (int ni = 0; ni < 8; ni++) {
                m = fmaxf(m, sc[ni][rh * 2]);
                m = fmaxf(m, sc[ni][rh * 2 + 1]);
            }
            m = fmaxf(m, __shfl_xor_sync(0xffffffffu, m, 1));
            m = fmaxf(m, __shfl_xor_sync(0xffffffffu, m, 2));
            float mnew = fmaxf(m_i[rh], m);
            float f = exp2f(m_i[rh] - mnew);
            float sum = 0.f;
#pragma unroll
            for (int ni = 0; ni < 8; ni++) {
                float x0 = sc[ni][rh * 2]     - mnew;
                float x1 = sc[ni][rh * 2 + 1] - mnew;
                float p0, p1;
                if (ni < 6) { p0 = exp2f(x0); p1 = exp2f(x1); }
                else        { p0 = fexp2(x0); p1 = fexp2(x1); }
                sc[ni][rh * 2]     = p0;
                sc[ni][rh * 2 + 1] = p1;
                sum += p0 + p1;
            }
            sum += __shfl_xor_sync(0xffffffffu, sum, 1);
            sum += __shfl_xor_sync(0xffffffffu, sum, 2);
            l_i[rh] = l_i[rh] * f + sum;
            m_i[rh] = mnew;
#pragma unroll
            for (int ni = 0; ni < 8; ni++) {
                oacc[ni][rh * 2]     *= f;
                oacc[ni][rh * 2 + 1] *= f;
            }
        }

#pragma unroll
        for (int ni = 0; ni < 8; ni++)
#pragma unroll
            for (int rh = 0; rh < 2; rh++) {
                uint2 pv;
                pv.x = f2tf32(sc[ni][rh * 2]);
                pv.y = f2tf32(sc[ni][rh * 2 + 1]);
                *(uint2*)&Ps[(w * 16 + lg + rh * 8) * TSTR + ni * 8 + lt * 2] = pv;
            }
        __syncwarp();

#pragma unroll
        for (int ks = 0; ks < 8; ks++) {
            uint32_t pa[4];
            const uint32_t* pp = Ps + (w * 16 + lg) * TSTR + ks * 8 + lt;
            pa[0] = pp[0];
            pa[1] = pp[8 * TSTR];
            pa[2] = pp[4];
            pa[3] = pp[8 * TSTR + 4];
#pragma unroll
            for (int ni = 0; ni < 8; ni++) {
                const uint32_t* p = Vs + (ni * 8 + lg) * TSTR + ks * 8 + lt;
                uint32_t b[2] = { p[0], p[4] };
                mma_tf32(oacc[ni], pa, b);
            }
        }
        __syncwarp();
    }

    // epilogue: normalize, tf32-round (feeds proj), write [B,S,E]
    const int b = bh >> 4;
    const int h = bh & 15;
    float inv[2] = { 1.f / l_i[0], 1.f / l_i[1] };
#pragma unroll
    for (int ni = 0; ni < 8; ni++)
#pragma unroll
        for (int rh = 0; rh < 2; rh++) {
            int s = q0 + w * 16 + lg + rh * 8;
            int e = h * 64 + ni * 8 + lt * 2;
            float2 v;
            v.x = __uint_as_float(f2tf32(oacc[ni][rh * 2]     * inv[rh]));
            v.y = __uint_as_float(f2tf32(oacc[ni][rh * 2 + 1] * inv[rh]));
            *(float2*)(g_attn + (size_t)(b * SS + s) * EE + e) = v;
        }
}

// ---------------------------------------------------------------------------
// Launch
// ---------------------------------------------------------------------------
extern "C" void kernel_launch(void* const* d_in, const int* in_sizes, int n_in,
                              void* d_out, int out_size)
{
    const float* x  = (const float*)d_in[0];
    const float* Wq = (const float*)d_in[1];
    const float* bq = (const float*)d_in[2];
    const float* Wk = (const float*)d_in[3];
    const float* bk = (const float*)d_in[4];
    const float* Wv = (const float*)d_in[5];
    const float* bv = (const float*)d_in[6];
    const float* Wo = (const float*)d_in[7];
    const float* bo = (const float*)d_in[8];
    float* out = (float*)d_out;

    (void)cudaFuncSetAttribute(qkv_mma,
                               cudaFuncAttributeMaxDynamicSharedMemorySize,
                               GEMM_SMEM);
    (void)cudaFuncSetAttribute(proj_mma,
                               cudaFuncAttributeMaxDynamicSharedMemorySize,
                               GEMM_SMEM);
    (void)cudaFuncSetAttribute(attn_kernel,
                               cudaFuncAttributeMaxDynamicSharedMemorySize,
                               ATTN_SMEM_BYTES);

    prep_x<<<1024, 256>>>(x);
    prep_w<<<dim3(32, 32, 4), 256>>>(Wq, Wk, Wv, Wo);

    dim3 gq(EE / GBN, NTOK / GBM, 3);
    qkv_mma<<<gq, 256, GEMM_SMEM>>>(bq, bk, bv);

    dim3 ga(SS / 64, BB * HH);
    attn_kernel<<<ga, 128, ATTN_SMEM_BYTES>>>();

    dim3 gp(EE / GBN, NTOK / GBM);
    proj_mma<<<gp, 256, GEMM_SMEM>>>(bo, out);
}

// round 8
// speedup vs baseline: 4.0172x; 1.0188x over previous
#include <cuda_runtime.h>
#include <math.h>
#include <stdint.h>

// Problem constants
#define BB   2
#define SS   2048
#define EE   1024
#define HH   16
#define DD   64
#define NTOK (BB * SS)   // 4096

// GEMM tiling: CTA 128x256xk32, 8 warps, warp tile 64x64
#define GBM 128
#define GBN 256
#define GBK 32
#define GNIT (EE / GBK)                 // 32
#define NSTG 3
#define A_BYTES (GBM * 128)             // 16384
#define B_BYTES (GBN * 128)             // 32768
#define STG_BYTES (A_BYTES + B_BYTES)   // 49152
#define GEMM_SMEM (NSTG * STG_BYTES)    // 147456

// Attention: Q/P, K, V tiles each 64 rows x 256B, swizzled
#define AT_QOFF 0
#define AT_KOFF 16384
#define AT_VOFF 32768
#define ATTN_SMEM_BYTES 49152

// ---------------------------------------------------------------------------
// Scratch
// ---------------------------------------------------------------------------
__device__ float g_x[NTOK * EE];             // x, tf32-rounded
__device__ float g_wt[4 * EE * EE];          // Wq^T,Wk^T,Wv^T,Wo^T, rounded
__device__ float g_q[BB * HH * SS * DD];     // [B,H,S,D]
__device__ float g_k[BB * HH * SS * DD];     // [B,H,S,D]
__device__ float g_v[BB * HH * SS * DD];     // [B,H,D,S] (transposed)
__device__ float g_attn[NTOK * EE];          // [B,S,E], tf32-rounded

// ---------------------------------------------------------------------------
// helpers
// ---------------------------------------------------------------------------
__device__ __forceinline__ uint32_t f2tf32(float f)
{
    uint32_t u;
    asm("cvt.rna.tf32.f32 %0, %1;" : "=r"(u) : "f"(f));
    return u;
}

__device__ __forceinline__ uint4 pack_tf32(float4 v)
{
    uint4 u;
    u.x = f2tf32(v.x); u.y = f2tf32(v.y); u.z = f2tf32(v.z); u.w = f2tf32(v.w);
    return u;
}

__device__ __forceinline__ void mma_tf32(float c[4], const uint32_t a[4],
                                         const uint32_t b[2])
{
    asm volatile(
        "mma.sync.aligned.m16n8k8.row.col.f32.tf32.tf32.f32 "
        "{%0,%1,%2,%3}, {%4,%5,%6,%7}, {%8,%9}, {%0,%1,%2,%3};"
        : "+f"(c[0]), "+f"(c[1]), "+f"(c[2]), "+f"(c[3])
        : "r"(a[0]), "r"(a[1]), "r"(a[2]), "r"(a[3]), "r"(b[0]), "r"(b[1]));
}

__device__ __forceinline__ uint32_t s2u(const void* p)
{
    return (uint32_t)__cvta_generic_to_shared(p);
}

__device__ __forceinline__ void cpa16(uint32_t dst, const void* src)
{
    asm volatile("cp.async.cg.shared.global [%0], [%1], 16;"
                 :: "r"(dst), "l"(src) : "memory");
}
__device__ __forceinline__ void cpa_commit()
{
    asm volatile("cp.async.commit_group;" ::: "memory");
}
__device__ __forceinline__ void cpa_wait1()
{
    asm volatile("cp.async.wait_group 1;" ::: "memory");
}

__device__ __forceinline__ void ldsm4(uint32_t* r, uint32_t a)
{
    asm volatile("ldmatrix.sync.aligned.m8n8.x4.shared.b16 {%0,%1,%2,%3}, [%4];"
                 : "=r"(r[0]), "=r"(r[1]), "=r"(r[2]), "=r"(r[3]) : "r"(a));
}

__device__ __forceinline__ void sts128(uint32_t a, uint4 v)
{
    asm volatile("st.shared.v4.b32 [%0], {%1,%2,%3,%4};"
                 :: "r"(a), "r"(v.x), "r"(v.y), "r"(v.z), "r"(v.w) : "memory");
}

__device__ __forceinline__ void sts64v(uint32_t a, uint32_t x, uint32_t y)
{
    asm volatile("st.shared.v2.b32 [%0], {%1,%2};"
                 :: "r"(a), "r"(x), "r"(y) : "memory");
}

// 16B-chunk swizzle within 64x256B tiles: chunk' = ((c&7)^(row&7)) | (c&8)
__device__ __forceinline__ uint32_t swz(int row, int c)
{
    return (uint32_t)(((((c) & 7) ^ ((row) & 7)) | ((c) & 8)) << 4);
}

// fast 2^x on the FMA pipe (x <= 0; Taylor deg-4, rel err ~4e-5)
__device__ __forceinline__ float fexp2(float x)
{
    x = fmaxf(x, -100.f);
    float z = x + 12582912.f;
    float f = x - (z - 12582912.f);
    float p = fmaf(f, 0.009618129f, 0.055504109f);
    p = fmaf(f, p, 0.240226507f);
    p = fmaf(f, p, 0.693147181f);
    p = fmaf(f, p, 1.0f);
    int e = (int)((unsigned)__float_as_int(z) << 23);
    return __int_as_float(__float_as_int(p) + e);
}

// ---------------------------------------------------------------------------
// Pre-pass: round x -> g_x
// ---------------------------------------------------------------------------
__global__ void __launch_bounds__(256)
prep_x(const float* __restrict__ x)
{
    const int i = blockIdx.x * 256 + threadIdx.x;
#pragma unroll
    for (int j = 0; j < 4; j++) {
        int idx = i + j * 262144;
        float4 v = ((const float4*)x)[idx];
        uint4 u = pack_tf32(v);
        float4 o;
        o.x = __uint_as_float(u.x); o.y = __uint_as_float(u.y);
        o.z = __uint_as_float(u.z); o.w = __uint_as_float(u.w);
        ((float4*)g_x)[idx] = o;
    }
}

// ---------------------------------------------------------------------------
// Pre-pass: transpose + round W -> g_wt
// ---------------------------------------------------------------------------
__global__ void __launch_bounds__(256)
prep_w(const float* __restrict__ Wq, const float* __restrict__ Wk,
       const float* __restrict__ Wv, const float* __restrict__ Wo)
{
    __shared__ float t[32][33];
    const float* W;
    if (blockIdx.z == 0)      W = Wq;
    else if (blockIdx.z == 1) W = Wk;
    else if (blockIdx.z == 2) W = Wv;
    else                      W = Wo;
    float* out = g_wt + (size_t)blockIdx.z * EE * EE;

    const int n0 = blockIdx.x * 32, k0 = blockIdx.y * 32;
    const int x = threadIdx.x & 31, y = threadIdx.x >> 5;
#pragma unroll
    for (int i = 0; i < 4; i++)
        t[y + 8 * i][x] = W[(size_t)(k0 + y + 8 * i) * EE + n0 + x];
    __syncthreads();
#pragma unroll
    for (int i = 0; i < 4; i++)
        out[(size_t)(n0 + y + 8 * i) * EE + k0 + x] =
            __uint_as_float(f2tf32(t[x][y + 8 * i]));
}

// ---------------------------------------------------------------------------
// GEMM core (unchanged from R7): C[128x256] = A[.,1024] @ Bt^T
// ---------------------------------------------------------------------------
__device__ __forceinline__ void gemm_core(const float* __restrict__ A,
                                          const float* __restrict__ Bt,
                                          int brow, int bcol,
                                          float c[4][8][4], char* sm)
{
    const int tid = threadIdx.x;
    const int w = tid >> 5, l = tid & 31;
    const int wm = w >> 2, wn = w & 3;
    const uint32_t sb = s2u(sm);

    const float* asrc[4]; uint32_t adst[4];
#pragma unroll
    for (int j = 0; j < 4; j++) {
        int idx = tid + 256 * j;
        int row = idx >> 3, kc = idx & 7;
        asrc[j] = A + (size_t)(brow + row) * EE + kc * 4;
        adst[j] = row * 128 + ((kc ^ (row & 7)) << 4);
    }
    const float* bsrc[8]; uint32_t bdst[8];
#pragma unroll
    for (int j = 0; j < 8; j++) {
        int idx = tid + 256 * j;
        int n = idx >> 3, kc = idx & 7;
        bsrc[j] = Bt + (size_t)(bcol + n) * EE + kc * 4;
        bdst[j] = A_BYTES + n * 128 + ((kc ^ (n & 7)) << 4);
    }

#pragma unroll
    for (int mi = 0; mi < 4; mi++)
#pragma unroll
        for (int ni = 0; ni < 8; ni++)
#pragma unroll
            for (int r = 0; r < 4; r++) c[mi][ni][r] = 0.f;

#pragma unroll
    for (int s = 0; s < 2; s++) {
        uint32_t so = sb + s * STG_BYTES;
        int k0 = s * GBK;
#pragma unroll
        for (int j = 0; j < 4; j++) cpa16(so + adst[j], asrc[j] + k0);
#pragma unroll
        for (int j = 0; j < 8; j++) cpa16(so + bdst[j], bsrc[j] + k0);
        cpa_commit();
    }

    const uint32_t abase = (uint32_t)((wm * 64 + (l & 15)) * 128);
    const int ahalf = l >> 4;
    const int axor = l & 7;
    const uint32_t bbase = (uint32_t)(A_BYTES +
                          (wn * 64 + (l & 7) + ((l >> 4) << 3)) * 128);
    const int bhalf = (l >> 3) & 1;
    const int bxor = l & 7;

    int stage = 0;
    for (int it = 0; it < GNIT; it++) {
        cpa_wait1();
        __syncthreads();

        if (it + 2 < GNIT) {
            int ls = (stage + 2) % NSTG;
            uint32_t so = sb + ls * STG_BYTES;
            int k0 = (it + 2) * GBK;
#pragma unroll
            for (int j = 0; j < 4; j++) cpa16(so + adst[j], asrc[j] + k0);
#pragma unroll
            for (int j = 0; j < 8; j++) cpa16(so + bdst[j], bsrc[j] + k0);
        }
        cpa_commit();

        const uint32_t so = sb + stage * STG_BYTES;
#pragma unroll
        for (int ks = 0; ks < 4; ks++) {
            uint32_t af[4][4], bf[4][4];
#pragma unroll
            for (int mi = 0; mi < 4; mi++)
                ldsm4(af[mi], so + abase + mi * 2048 +
                      ((uint32_t)((2 * ks + ahalf) ^ axor) << 4));
#pragma unroll
            for (int n2 = 0; n2 < 4; n2++)
                ldsm4(bf[n2], so + bbase + n2 * 2048 +
                      ((uint32_t)((2 * ks + bhalf) ^ bxor) << 4));
#pragma unroll
            for (int mi = 0; mi < 4; mi++)
#pragma unroll
                for (int n2 = 0; n2 < 4; n2++) {
                    mma_tf32(c[mi][2 * n2],     af[mi], &bf[n2][0]);
                    mma_tf32(c[mi][2 * n2 + 1], af[mi], &bf[n2][2]);
                }
        }
        stage = (stage + 1) % NSTG;
    }
}

// ---------------------------------------------------------------------------
// QKV: grid (4, 32, 3)
// ---------------------------------------------------------------------------
__global__ void __launch_bounds__(256, 1)
qkv_mma(const float* __restrict__ bq, const float* __restrict__ bk,
        const float* __restrict__ bv)
{
    extern __shared__ char smc[];
    const float* bias;
    if (blockIdx.z == 0)      bias = bq;
    else if (blockIdx.z == 1) bias = bk;
    else                      bias = bv;
    const float* Bt = g_wt + (size_t)blockIdx.z * EE * EE;

    const int brow = blockIdx.y * GBM;
    const int bcol = blockIdx.x * GBN;

    float c[4][8][4];
    gemm_core(g_x, Bt, brow, bcol, c, smc);

    const int tid = threadIdx.x;
    const int w = tid >> 5, l = tid & 31;
    const int wm = w >> 2, wn = w & 3;

#pragma unroll
    for (int mi = 0; mi < 4; mi++)
#pragma unroll
        for (int ni = 0; ni < 8; ni++) {
            int row0 = brow + wm * 64 + mi * 16 + (l >> 2);
            int col  = bcol + wn * 64 + ni * 8 + (l & 3) * 2;
            float b0 = bias[col], b1 = bias[col + 1];
            int h = col >> 6, d = col & 63;
#pragma unroll
            for (int half = 0; half < 2; half++) {
                int t = row0 + half * 8;
                int b = t >> 11, s = t & 2047;
                float v0 = c[mi][ni][half * 2 + 0] + b0;
                float v1 = c[mi][ni][half * 2 + 1] + b1;
                if (blockIdx.z < 2) {
                    float* dst = (blockIdx.z == 0) ? g_q : g_k;
                    float2 v; v.x = v0; v.y = v1;
                    *(float2*)(dst + ((size_t)(b * HH + h) * SS + s) * DD + d) = v;
                } else {
                    size_t base = (size_t)(b * HH + h) * DD;
                    g_v[(base + d)     * SS + s] = v0;
                    g_v[(base + d + 1) * SS + s] = v1;
                }
            }
        }
}

// ---------------------------------------------------------------------------
// Out-proj: grid (4, 32)
// ---------------------------------------------------------------------------
__global__ void __launch_bounds__(256, 1)
proj_mma(const float* __restrict__ bo, float* __restrict__ out)
{
    extern __shared__ char smc[];
    const float* Bt = g_wt + (size_t)3 * EE * EE;

    const int brow = blockIdx.y * GBM;
    const int bcol = blockIdx.x * GBN;

    float c[4][8][4];
    gemm_core(g_attn, Bt, brow, bcol, c, smc);

    const int tid = threadIdx.x;
    const int w = tid >> 5, l = tid & 31;
    const int wm = w >> 2, wn = w & 3;

#pragma unroll
    for (int mi = 0; mi < 4; mi++)
#pragma unroll
        for (int ni = 0; ni < 8; ni++) {
            int row0 = brow + wm * 64 + mi * 16 + (l >> 2);
            int col  = bcol + wn * 64 + ni * 8 + (l & 3) * 2;
            float b0 = bo[col], b1 = bo[col + 1];
#pragma unroll
            for (int half = 0; half < 2; half++) {
                int row = row0 + half * 8;
                float2 v;
                v.x = c[mi][ni][half * 2 + 0] + b0;
                v.y = c[mi][ni][half * 2 + 1] + b1;
                *(float2*)(out + (size_t)row * EE + col) = v;
            }
        }
}

// ---------------------------------------------------------------------------
// Flash attention, tf32 mma.sync + ldmatrix fragments, causal, base-2 softmax.
// grid (32, 32): x -> qt (reversed), y -> bh. 128 threads = 4 warps.
// Tiles: Q(->P reuse)/K/V, 64 rows x 256B swizzled.
// ---------------------------------------------------------------------------
__global__ void __launch_bounds__(128, 3)
attn_kernel()
{
    extern __shared__ char smc[];
    const uint32_t sb = s2u(smc);

    const int tid = threadIdx.x;
    const int w = tid >> 5, l = tid & 31;
    const int lg = l >> 2, lt = l & 3;
    const int qt = (gridDim.x - 1) - blockIdx.x;
    const int bh = blockIdx.y;
    const int q0 = qt * 64;

    const float* Qg = g_q + (size_t)bh * SS * DD;
    const float* Kg = g_k + (size_t)bh * SS * DD;
    const float* Vg = g_v + (size_t)bh * DD * SS;   // [D,S]

    // Q scale folds 1/sqrt(D) and log2(e)
    const float qscale = 0.125f * 1.44269504f;
#pragma unroll
    for (int j = 0; j < 8; j++) {
        int p = tid + 128 * j;
        int r = p >> 4, c4 = p & 15;
        float4 v = *(const float4*)(Qg + (size_t)(q0 + r) * DD + c4 * 4);
        v.x *= qscale; v.y *= qscale; v.z *= qscale; v.w *= qscale;
        sts128(sb + AT_QOFF + r * 256 + swz(r, c4), pack_tf32(v));
    }
    __syncthreads();

    // hoist Q A-fragments (ldmatrix)
    const int arow = w * 16 + (l & 15);
    const int ach = l >> 4;
    uint32_t qa[8][4];
#pragma unroll
    for (int ks = 0; ks < 8; ks++)
        ldsm4(qa[ks], sb + AT_QOFF + arow * 256 + swz(arow, 2 * ks + ach));
    __syncthreads();   // Qs becomes Ps

    // B-frag lane addressing (shared by K and V)
    const int brow_base = (l & 7) + ((l >> 4) << 3);
    const int bch = (l >> 3) & 1;

    float m_i[2] = { -1e30f, -1e30f };
    float l_i[2] = { 0.f, 0.f };
    float oacc[8][4];
#pragma unroll
    for (int ni = 0; ni < 8; ni++)
#pragma unroll
        for (int r = 0; r < 4; r++) oacc[ni][r] = 0.f;

    for (int jt = 0; jt <= qt; jt++) {
        const int k0 = jt * 64;
        __syncthreads();
#pragma unroll
        for (int j = 0; j < 8; j++) {
            int p = tid + 128 * j;
            int r = p >> 4, c4 = p & 15;
            float4 kv4 = *(const float4*)(Kg + (size_t)(k0 + r) * DD + c4 * 4);
            sts128(sb + AT_KOFF + r * 256 + swz(r, c4), pack_tf32(kv4));
            float4 vv4 = *(const float4*)(Vg + (size_t)r * SS + k0 + c4 * 4);
            sts128(sb + AT_VOFF + r * 256 + swz(r, c4), pack_tf32(vv4));
        }
        __syncthreads();

        // ---- S = Q @ K^T ----
        float sc[8][4];
#pragma unroll
        for (int ni = 0; ni < 8; ni++)
#pragma unroll
            for (int r = 0; r < 4; r++) sc[ni][r] = 0.f;

#pragma unroll
        for (int ks = 0; ks < 8; ks++) {
#pragma unroll
            for (int n2 = 0; n2 < 4; n2++) {
                uint32_t kf[4];
                int br = n2 * 16 + brow_base;
                ldsm4(kf, sb + AT_KOFF + br * 256 + swz(br, 2 * ks + bch));
                mma_tf32(sc[2 * n2],     qa[ks], &kf[0]);
                mma_tf32(sc[2 * n2 + 1], qa[ks], &kf[2]);
            }
        }

        // ---- causal mask on diagonal tile ----
        if (jt == qt) {
#pragma unroll
            for (int ni = 0; ni < 8; ni++)
#pragma unroll
                for (int r = 0; r < 4; r++) {
                    int row = w * 16 + lg + (r >> 1) * 8;
                    int col = ni * 8 + lt * 2 + (r & 1);
                    if (col > row) sc[ni][r] = -1e30f;
                }
        }

        // ---- online softmax (base 2, hybrid MUFU/FMA exp) ----
#pragma unroll
        for (int rh = 0; rh < 2; rh++) {
            float m = -1e30f;
#pragma unroll
            for (int ni = 0; ni < 8; ni++) {
                m = fmaxf(m, sc[ni][rh * 2]);
                m = fmaxf(m, sc[ni][rh * 2 + 1]);
            }
            m = fmaxf(m, __shfl_xor_sync(0xffffffffu, m, 1));
            m = fmaxf(m, __shfl_xor_sync(0xffffffffu, m, 2));
            float mnew = fmaxf(m_i[rh], m);
            float f = exp2f(m_i[rh] - mnew);
            float sum = 0.f;
#pragma unroll
            for (int ni = 0; ni < 8; ni++) {
                float x0 = sc[ni][rh * 2]     - mnew;
                float x1 = sc[ni][rh * 2 + 1] - mnew;
                float p0, p1;
                if (ni < 6) { p0 = exp2f(x0); p1 = exp2f(x1); }
                else        { p0 = fexp2(x0); p1 = fexp2(x1); }
                sc[ni][rh * 2]     = p0;
                sc[ni][rh * 2 + 1] = p1;
                sum += p0 + p1;
            }
            sum += __shfl_xor_sync(0xffffffffu, sum, 1);
            sum += __shfl_xor_sync(0xffffffffu, sum, 2);
            l_i[rh] = l_i[rh] * f + sum;
            m_i[rh] = mnew;
#pragma unroll
            for (int ni = 0; ni < 8; ni++) {
                oacc[ni][rh * 2]     *= f;
                oacc[ni][rh * 2 + 1] *= f;
            }
        }

        // ---- write P into swizzled Q/P tile (warp-private rows) ----
#pragma unroll
        for (int ni = 0; ni < 8; ni++)
#pragma unroll
            for (int rh = 0; rh < 2; rh++) {
                int row = w * 16 + lg + rh * 8;
                int c = ni * 2 + (lt >> 1);
                sts64v(sb + AT_QOFF + row * 256 + swz(row, c) + (lt & 1) * 8,
                       f2tf32(sc[ni][rh * 2]), f2tf32(sc[ni][rh * 2 + 1]));
            }
        __syncwarp();

        // ---- O += P @ V ----
#pragma unroll
        for (int ks = 0; ks < 8; ks++) {
            uint32_t pa[4];
            ldsm4(pa, sb + AT_QOFF + arow * 256 + swz(arow, 2 * ks + ach));
#pragma unroll
            for (int n2 = 0; n2 < 4; n2++) {
                uint32_t vf[4];
                int vr = n2 * 16 + brow_base;
                ldsm4(vf, sb + AT_VOFF + vr * 256 + swz(vr, 2 * ks + bch));
                mma_tf32(oacc[2 * n2],     pa, &vf[0]);
                mma_tf32(oacc[2 * n2 + 1], pa, &vf[2]);
            }
        }
        __syncwarp();
    }

    // ---- epilogue: normalize, tf32-round (feeds proj), write [B,S,E] ----
    const int b = bh >> 4;
    const int h = bh & 15;
    float inv[2] = { 1.f / l_i[0], 1.f / l_i[1] };
#pragma unroll
    for (int ni = 0; ni < 8; ni++)
#pragma unroll
        for (int rh = 0; rh < 2; rh++) {
            int s = q0 + w * 16 + lg + rh * 8;
            int e = h * 64 + ni * 8 + lt * 2;
            float2 v;
            v.x = __uint_as_float(f2tf32(oacc[ni][rh * 2]     * inv[rh]));
            v.y = __uint_as_float(f2tf32(oacc[ni][rh * 2 + 1] * inv[rh]));
            *(float2*)(g_attn + (size_t)(b * SS + s) * EE + e) = v;
        }
}

// ---------------------------------------------------------------------------
// Launch
// ---------------------------------------------------------------------------
extern "C" void kernel_launch(void* const* d_in, const int* in_sizes, int n_in,
                              void* d_out, int out_size)
{
    const float* x  = (const float*)d_in[0];
    const float* Wq = (const float*)d_in[1];
    const float* bq = (const float*)d_in[2];
    const float* Wk = (const float*)d_in[3];
    const float* bk = (const float*)d_in[4];
    const float* Wv = (const float*)d_in[5];
    const float* bv = (const float*)d_in[6];
    const float* Wo = (const float*)d_in[7];
    const float* bo = (const float*)d_in[8];
    float* out = (float*)d_out;

    (void)cudaFuncSetAttribute(qkv_mma,
                               cudaFuncAttributeMaxDynamicSharedMemorySize,
                               GEMM_SMEM);
    (void)cudaFuncSetAttribute(proj_mma,
                               cudaFuncAttributeMaxDynamicSharedMemorySize,
                               GEMM_SMEM);
    (void)cudaFuncSetAttribute(attn_kernel,
                               cudaFuncAttributeMaxDynamicSharedMemorySize,
                               ATTN_SMEM_BYTES);

    prep_x<<<1024, 256>>>(x);
    prep_w<<<dim3(32, 32, 4), 256>>>(Wq, Wk, Wv, Wo);

    dim3 gq(EE / GBN, NTOK / GBM, 3);
    qkv_mma<<<gq, 256, GEMM_SMEM>>>(bq, bk, bv);

    dim3 ga(SS / 64, BB * HH);
    attn_kernel<<<ga, 128, ATTN_SMEM_BYTES>>>();

    dim3 gp(EE / GBN, NTOK / GBM);
    proj_mma<<<gp, 256, GEMM_SMEM>>>(bo, out);
}

// round 10
// speedup vs baseline: 4.1499x; 1.0330x over previous
#include <cuda_runtime.h>
#include <math.h>
#include <stdint.h>

// Problem constants
#define BB   2
#define SS   2048
#define EE   1024
#define HH   16
#define DD   64
#define NTOK (BB * SS)   // 4096

// GEMM tiling: CTA 128x256xk32, 8 warps, warp tile 64x64
#define GBM 128
#define GBN 256
#define GBK 32
#define GNIT (EE / GBK)                 // 32
#define NSTG 3
#define A_BYTES (GBM * 128)             // 16384
#define B_BYTES (GBN * 128)             // 32768
#define STG_BYTES (A_BYTES + B_BYTES)   // 49152
#define GEMM_SMEM (NSTG * STG_BYTES)    // 147456

// Attention: CTA q-tile 128, kv-tile 64, 4 warps (32 q-rows each)
// smem: [stage0: K 16K | V 16K][stage1: K 16K | V 16K][Q/P 32K] = 96KB
#define AT_STG 32768
#define AT_V   16384
#define AT_P   65536
#define ATTN_SMEM_BYTES 98304

// ---------------------------------------------------------------------------
// Scratch
// ---------------------------------------------------------------------------
__device__ float g_x[NTOK * EE];             // x, tf32-rounded
__device__ float g_wt[4 * EE * EE];          // Wq^T,Wk^T,Wv^T,Wo^T, rounded
__device__ float g_q[BB * HH * SS * DD];     // [B,H,S,D]
__device__ float g_k[BB * HH * SS * DD];     // [B,H,S,D], tf32-rounded
__device__ float g_v[BB * HH * SS * DD];     // [B,H,D,S] transposed, rounded
__device__ float g_attn[NTOK * EE];          // [B,S,E], tf32-rounded

// ---------------------------------------------------------------------------
// helpers
// ---------------------------------------------------------------------------
__device__ __forceinline__ uint32_t f2tf32(float f)
{
    uint32_t u;
    asm("cvt.rna.tf32.f32 %0, %1;" : "=r"(u) : "f"(f));
    return u;
}

__device__ __forceinline__ uint4 pack_tf32(float4 v)
{
    uint4 u;
    u.x = f2tf32(v.x); u.y = f2tf32(v.y); u.z = f2tf32(v.z); u.w = f2tf32(v.w);
    return u;
}

__device__ __forceinline__ void mma_tf32(float c[4], const uint32_t a[4],
                                         const uint32_t b[2])
{
    asm volatile(
        "mma.sync.aligned.m16n8k8.row.col.f32.tf32.tf32.f32 "
        "{%0,%1,%2,%3}, {%4,%5,%6,%7}, {%8,%9}, {%0,%1,%2,%3};"
        : "+f"(c[0]), "+f"(c[1]), "+f"(c[2]), "+f"(c[3])
        : "r"(a[0]), "r"(a[1]), "r"(a[2]), "r"(a[3]), "r"(b[0]), "r"(b[1]));
}

__device__ __forceinline__ uint32_t s2u(const void* p)
{
    return (uint32_t)__cvta_generic_to_shared(p);
}

__device__ __forceinline__ void cpa16(uint32_t dst, const void* src)
{
    asm volatile("cp.async.cg.shared.global [%0], [%1], 16;"
                 :: "r"(dst), "l"(src) : "memory");
}
__device__ __forceinline__ void cpa_commit()
{
    asm volatile("cp.async.commit_group;" ::: "memory");
}
__device__ __forceinline__ void cpa_wait1()
{
    asm volatile("cp.async.wait_group 1;" ::: "memory");
}
__device__ __forceinline__ void cpa_wait0()
{
    asm volatile("cp.async.wait_group 0;" ::: "memory");
}

__device__ __forceinline__ void ldsm4(uint32_t* r, uint32_t a)
{
    asm volatile("ldmatrix.sync.aligned.m8n8.x4.shared.b16 {%0,%1,%2,%3}, [%4];"
                 : "=r"(r[0]), "=r"(r[1]), "=r"(r[2]), "=r"(r[3]) : "r"(a));
}

__device__ __forceinline__ void sts128(uint32_t a, uint4 v)
{
    asm volatile("st.shared.v4.b32 [%0], {%1,%2,%3,%4};"
                 :: "r"(a), "r"(v.x), "r"(v.y), "r"(v.z), "r"(v.w) : "memory");
}

__device__ __forceinline__ void sts64v(uint32_t a, uint32_t x, uint32_t y)
{
    asm volatile("st.shared.v2.b32 [%0], {%1,%2};"
                 :: "r"(a), "r"(x), "r"(y) : "memory");
}

// 16B-chunk swizzle within rows of 256B: chunk' = ((c&7)^(row&7)) | (c&8)
__device__ __forceinline__ uint32_t swz(int row, int c)
{
    return (uint32_t)(((((c) & 7) ^ ((row) & 7)) | ((c) & 8)) << 4);
}

// fast 2^x on the FMA pipe (x <= 0; rel err ~4e-5)
__device__ __forceinline__ float fexp2(float x)
{
    x = fmaxf(x, -100.f);
    float z = x + 12582912.f;
    float f = x - (z - 12582912.f);
    float p = fmaf(f, 0.009618129f, 0.055504109f);
    p = fmaf(f, p, 0.240226507f);
    p = fmaf(f, p, 0.693147181f);
    p = fmaf(f, p, 1.0f);
    int e = (int)((unsigned)__float_as_int(z) << 23);
    return __int_as_float(__float_as_int(p) + e);
}

// ---------------------------------------------------------------------------
// Pre-pass: round x -> g_x
// ---------------------------------------------------------------------------
__global__ void __launch_bounds__(256)
prep_x(const float* __restrict__ x)
{
    const int i = blockIdx.x * 256 + threadIdx.x;
#pragma unroll
    for (int j = 0; j < 4; j++) {
        int idx = i + j * 262144;
        float4 v = ((const float4*)x)[idx];
        uint4 u = pack_tf32(v);
        float4 o;
        o.x = __uint_as_float(u.x); o.y = __uint_as_float(u.y);
        o.z = __uint_as_float(u.z); o.w = __uint_as_float(u.w);
        ((float4*)g_x)[idx] = o;
    }
}

// ---------------------------------------------------------------------------
// Pre-pass: transpose + round W -> g_wt
// ---------------------------------------------------------------------------
__global__ void __launch_bounds__(256)
prep_w(const float* __restrict__ Wq, const float* __restrict__ Wk,
       const float* __restrict__ Wv, const float* __restrict__ Wo)
{
    __shared__ float t[32][33];
    const float* W;
    if (blockIdx.z == 0)      W = Wq;
    else if (blockIdx.z == 1) W = Wk;
    else if (blockIdx.z == 2) W = Wv;
    else                      W = Wo;
    float* out = g_wt + (size_t)blockIdx.z * EE * EE;

    const int n0 = blockIdx.x * 32, k0 = blockIdx.y * 32;
    const int x = threadIdx.x & 31, y = threadIdx.x >> 5;
#pragma unroll
    for (int i = 0; i < 4; i++)
        t[y + 8 * i][x] = W[(size_t)(k0 + y + 8 * i) * EE + n0 + x];
    __syncthreads();
#pragma unroll
    for (int i = 0; i < 4; i++)
        out[(size_t)(n0 + y + 8 * i) * EE + k0 + x] =
            __uint_as_float(f2tf32(t[x][y + 8 * i]));
}

// ---------------------------------------------------------------------------
// GEMM core (unchanged): C[128x256] = A[.,1024] @ Bt^T
// ---------------------------------------------------------------------------
__device__ __forceinline__ void gemm_core(const float* __restrict__ A,
                                          const float* __restrict__ Bt,
                                          int brow, int bcol,
                                          float c[4][8][4], char* sm)
{
    const int tid = threadIdx.x;
    const int w = tid >> 5, l = tid & 31;
    const int wm = w >> 2, wn = w & 3;
    const uint32_t sb = s2u(sm);

    const float* asrc[4]; uint32_t adst[4];
#pragma unroll
    for (int j = 0; j < 4; j++) {
        int idx = tid + 256 * j;
        int row = idx >> 3, kc = idx & 7;
        asrc[j] = A + (size_t)(brow + row) * EE + kc * 4;
        adst[j] = row * 128 + ((kc ^ (row & 7)) << 4);
    }
    const float* bsrc[8]; uint32_t bdst[8];
#pragma unroll
    for (int j = 0; j < 8; j++) {
        int idx = tid + 256 * j;
        int n = idx >> 3, kc = idx & 7;
        bsrc[j] = Bt + (size_t)(bcol + n) * EE + kc * 4;
        bdst[j] = A_BYTES + n * 128 + ((kc ^ (n & 7)) << 4);
    }

#pragma unroll
    for (int mi = 0; mi < 4; mi++)
#pragma unroll
        for (int ni = 0; ni < 8; ni++)
#pragma unroll
            for (int r = 0; r < 4; r++) c[mi][ni][r] = 0.f;

#pragma unroll
    for (int s = 0; s < 2; s++) {
        uint32_t so = sb + s * STG_BYTES;
        int k0 = s * GBK;
#pragma unroll
        for (int j = 0; j < 4; j++) cpa16(so + adst[j], asrc[j] + k0);
#pragma unroll
        for (int j = 0; j < 8; j++) cpa16(so + bdst[j], bsrc[j] + k0);
        cpa_commit();
    }

    const uint32_t abase = (uint32_t)((wm * 64 + (l & 15)) * 128);
    const int ahalf = l >> 4;
    const int axor = l & 7;
    const uint32_t bbase = (uint32_t)(A_BYTES +
                          (wn * 64 + (l & 7) + ((l >> 4) << 3)) * 128);
    const int bhalf = (l >> 3) & 1;
    const int bxor = l & 7;

    int stage = 0;
    for (int it = 0; it < GNIT; it++) {
        cpa_wait1();
        __syncthreads();

        if (it + 2 < GNIT) {
            int ls = (stage + 2) % NSTG;
            uint32_t so = sb + ls * STG_BYTES;
            int k0 = (it + 2) * GBK;
#pragma unroll
            for (int j = 0; j < 4; j++) cpa16(so + adst[j], asrc[j] + k0);
#pragma unroll
            for (int j = 0; j < 8; j++) cpa16(so + bdst[j], bsrc[j] + k0);
        }
        cpa_commit();

        const uint32_t so = sb + stage * STG_BYTES;
#pragma unroll
        for (int ks = 0; ks < 4; ks++) {
            uint32_t af[4][4], bf[4][4];
#pragma unroll
            for (int mi = 0; mi < 4; mi++)
                ldsm4(af[mi], so + abase + mi * 2048 +
                      ((uint32_t)((2 * ks + ahalf) ^ axor) << 4));
#pragma unroll
            for (int n2 = 0; n2 < 4; n2++)
                ldsm4(bf[n2], so + bbase + n2 * 2048 +
                      ((uint32_t)((2 * ks + bhalf) ^ bxor) << 4));
#pragma unroll
            for (int mi = 0; mi < 4; mi++)
#pragma unroll
                for (int n2 = 0; n2 < 4; n2++) {
                    mma_tf32(c[mi][2 * n2],     af[mi], &bf[n2][0]);
                    mma_tf32(c[mi][2 * n2 + 1], af[mi], &bf[n2][2]);
                }
        }
        stage = (stage + 1) % NSTG;
    }
}

// ---------------------------------------------------------------------------
// QKV: grid (4, 32, 3). K and V written tf32-pre-rounded (cp.async-ready).
// ---------------------------------------------------------------------------
__global__ void __launch_bounds__(256, 1)
qkv_mma(const float* __restrict__ bq, const float* __restrict__ bk,
        const float* __restrict__ bv)
{
    extern __shared__ char smc[];
    const float* bias;
    if (blockIdx.z == 0)      bias = bq;
    else if (blockIdx.z == 1) bias = bk;
    else                      bias = bv;
    const float* Bt = g_wt + (size_t)blockIdx.z * EE * EE;

    const int brow = blockIdx.y * GBM;
    const int bcol = blockIdx.x * GBN;

    float c[4][8][4];
    gemm_core(g_x, Bt, brow, bcol, c, smc);

    const int tid = threadIdx.x;
    const int w = tid >> 5, l = tid & 31;
    const int wm = w >> 2, wn = w & 3;

#pragma unroll
    for (int mi = 0; mi < 4; mi++)
#pragma unroll
        for (int ni = 0; ni < 8; ni++) {
            int row0 = brow + wm * 64 + mi * 16 + (l >> 2);
            int col  = bcol + wn * 64 + ni * 8 + (l & 3) * 2;
            float b0 = bias[col], b1 = bias[col + 1];
            int h = col >> 6, d = col & 63;
#pragma unroll
            for (int half = 0; half < 2; half++) {
                int t = row0 + half * 8;
                int b = t >> 11, s = t & 2047;
                float v0 = c[mi][ni][half * 2 + 0] + b0;
                float v1 = c[mi][ni][half * 2 + 1] + b1;
                if (blockIdx.z == 0) {
                    float2 v; v.x = v0; v.y = v1;
                    *(float2*)(g_q + ((size_t)(b * HH + h) * SS + s) * DD + d) = v;
                } else if (blockIdx.z == 1) {
                    float2 v;
                    v.x = __uint_as_float(f2tf32(v0));
                    v.y = __uint_as_float(f2tf32(v1));
                    *(float2*)(g_k + ((size_t)(b * HH + h) * SS + s) * DD + d) = v;
                } else {
                    size_t base = (size_t)(b * HH + h) * DD;
                    g_v[(base + d)     * SS + s] = __uint_as_float(f2tf32(v0));
                    g_v[(base + d + 1) * SS + s] = __uint_as_float(f2tf32(v1));
                }
            }
        }
}

// ---------------------------------------------------------------------------
// Out-proj: grid (4, 32)
// ---------------------------------------------------------------------------
__global__ void __launch_bounds__(256, 1)
proj_mma(const float* __restrict__ bo, float* __restrict__ out)
{
    extern __shared__ char smc[];
    const float* Bt = g_wt + (size_t)3 * EE * EE;

    const int brow = blockIdx.y * GBM;
    const int bcol = blockIdx.x * GBN;

    float c[4][8][4];
    gemm_core(g_attn, Bt, brow, bcol, c, smc);

    const int tid = threadIdx.x;
    const int w = tid >> 5, l = tid & 31;
    const int wm = w >> 2, wn = w & 3;

#pragma unroll
    for (int mi = 0; mi < 4; mi++)
#pragma unroll
        for (int ni = 0; ni < 8; ni++) {
            int row0 = brow + wm * 64 + mi * 16 + (l >> 2);
            int col  = bcol + wn * 64 + ni * 8 + (l & 3) * 2;
            float b0 = bo[col], b1 = bo[col + 1];
#pragma unroll
            for (int half = 0; half < 2; half++) {
                int row = row0 + half * 8;
                float2 v;
                v.x = c[mi][ni][half * 2 + 0] + b0;
                v.y = c[mi][ni][half * 2 + 1] + b1;
                *(float2*)(out + (size_t)row * EE + col) = v;
            }
        }
}

// ---------------------------------------------------------------------------
// Flash attention v2: CTA q-tile 128, kv-tile 64, 4 warps x 32 q-rows.
// cp.async double-buffered K/V; ldmatrix fragments; base-2 hybrid softmax.
// grid (16, 32): x -> qt (reversed), y -> bh.
// ---------------------------------------------------------------------------
__global__ void __launch_bounds__(128, 2)
attn_kernel()
{
    extern __shared__ char smc[];
    const uint32_t sb = s2u(smc);

    const int tid = threadIdx.x;
    const int w = tid >> 5, l = tid & 31;
    const int lg = l >> 2, lt = l & 3;
    const int qt = (gridDim.x - 1) - blockIdx.x;
    const int bh = blockIdx.y;
    const int q0 = qt * 128;

    const float* Qg = g_q + (size_t)bh * SS * DD;
    const float* Kg = g_k + (size_t)bh * SS * DD;
    const float* Vg = g_v + (size_t)bh * DD * SS;   // [D,S]

    const int jmax = 2 * qt + 2;

    // cp.async K/V mappings: 8 K chunks + 8 V chunks per thread per tile
    const float* ksrc[8]; const float* vsrc[8];
    uint32_t kdst[8], vdst[8];
#pragma unroll
    for (int j2 = 0; j2 < 8; j2++) {
        int idx = tid + 128 * j2;
        int r = idx >> 4, c = idx & 15;
        ksrc[j2] = Kg + (size_t)r * DD + c * 4;          // + k0*DD
        kdst[j2] = r * 256 + swz(r, c);
        vsrc[j2] = Vg + (size_t)r * SS + c * 4;          // + k0
        vdst[j2] = AT_V + r * 256 + swz(r, c);
    }

    // prologue: fetch kv-tile 0 into stage 0
#pragma unroll
    for (int j2 = 0; j2 < 8; j2++) {
        cpa16(sb + kdst[j2], ksrc[j2]);
        cpa16(sb + vdst[j2], vsrc[j2]);
    }
    cpa_commit();

    // load Q tile (scaled + rounded) into P region, hoist fragments
    const float qscale = 0.125f * 1.44269504f;
#pragma unroll
    for (int j = 0; j < 16; j++) {
        int p = tid + 128 * j;
        int r = p >> 4, c4 = p & 15;
        float4 v = *(const float4*)(Qg + (size_t)(q0 + r) * DD + c4 * 4);
        v.x *= qscale; v.y *= qscale; v.z *= qscale; v.w *= qscale;
        sts128(sb + AT_P + r * 256 + swz(r, c4), pack_tf32(v));
    }
    __syncthreads();

    const int arow_l = l & 15;
    const int ach = l >> 4;
    uint32_t qa[2][8][4];
#pragma unroll
    for (int g = 0; g < 2; g++) {
        int row = w * 32 + g * 16 + arow_l;
#pragma unroll
        for (int ks = 0; ks < 8; ks++)
            ldsm4(qa[g][ks], sb + AT_P + row * 256 + swz(row, 2 * ks + ach));
    }

    const int brow_base = (l & 7) + ((l >> 4) << 3);
    const int bch = (l >> 3) & 1;

    float m_i[2][2], l_i[2][2];
#pragma unroll
    for (int g = 0; g < 2; g++)
#pragma unroll
        for (int rh = 0; rh < 2; rh++) { m_i[g][rh] = -1e30f; l_i[g][rh] = 0.f; }

    float oacc[2][8][4];
#pragma unroll
    for (int g = 0; g < 2; g++)
#pragma unroll
        for (int ni = 0; ni < 8; ni++)
#pragma unroll
            for (int r = 0; r < 4; r++) oacc[g][ni][r] = 0.f;

    for (int j = 0; j < jmax; j++) {
        const int k0 = j * 64;
        const uint32_t so = sb + (j & 1) * AT_STG;

        cpa_wait0();
        __syncthreads();   // kv tile j visible; all warps done with other stage

        if (j + 1 < jmax) {
            const uint32_t sn = sb + ((j + 1) & 1) * AT_STG;
            const int kn = (j + 1) * 64;
#pragma unroll
            for (int j2 = 0; j2 < 8; j2++) {
                cpa16(sn + kdst[j2], ksrc[j2] + (size_t)kn * DD);
                cpa16(sn + vdst[j2], vsrc[j2] + kn);
            }
        }
        cpa_commit();

        // warp active if any of its rows can attend this kv tile
        const bool active = (k0 <= q0 + w * 32 + 31);
        if (active) {
#pragma unroll
            for (int g = 0; g < 2; g++) {
                // ---- S = Q @ K^T for this 16-row group ----
                float sc[8][4];
#pragma unroll
                for (int ni = 0; ni < 8; ni++)
#pragma unroll
                    for (int r = 0; r < 4; r++) sc[ni][r] = 0.f;

#pragma unroll
                for (int ks = 0; ks < 8; ks++) {
#pragma unroll
                    for (int n2 = 0; n2 < 4; n2++) {
                        uint32_t kf[4];
                        int br = n2 * 16 + brow_base;
                        ldsm4(kf, so + br * 256 + swz(br, 2 * ks + bch));
                        mma_tf32(sc[2 * n2],     qa[g][ks], &kf[0]);
                        mma_tf32(sc[2 * n2 + 1], qa[g][ks], &kf[2]);
                    }
                }

                // ---- causal mask (only possible on the last two tiles) ----
                if (j >= 2 * qt) {
#pragma unroll
                    for (int ni = 0; ni < 8; ni++)
#pragma unroll
                        for (int r = 0; r < 4; r++) {
                            int row = q0 + w * 32 + g * 16 + lg + (r >> 1) * 8;
                            int col = k0 + ni * 8 + lt * 2 + (r & 1);
                            if (col > row) sc[ni][r] = -1e30f;
                        }
                }

                // ---- online softmax (base 2, hybrid exp) ----
#pragma unroll
                for (int rh = 0; rh < 2; rh++) {
                    float m = -1e30f;
#pragma unroll
                    for (int ni = 0; ni < 8; ni++) {
                        m = fmaxf(m, sc[ni][rh * 2]);
                        m = fmaxf(m, sc[ni][rh * 2 + 1]);
                    }
                    m = fmaxf(m, __shfl_xor_sync(0xffffffffu, m, 1));
                    m = fmaxf(m, __shfl_xor_sync(0xffffffffu, m, 2));
                    float mnew = fmaxf(m_i[g][rh], m);
                    float f = exp2f(m_i[g][rh] - mnew);
                    float sum = 0.f;
#pragma unroll
                    for (int ni = 0; ni < 8; ni++) {
                        float x0 = sc[ni][rh * 2]     - mnew;
                        float x1 = sc[ni][rh * 2 + 1] - mnew;
                        float p0, p1;
                        if (ni < 6) { p0 = exp2f(x0); p1 = exp2f(x1); }
                        else        { p0 = fexp2(x0); p1 = fexp2(x1); }
                        sc[ni][rh * 2]     = p0;
                        sc[ni][rh * 2 + 1] = p1;
                        sum += p0 + p1;
                    }
                    sum += __shfl_xor_sync(0xffffffffu, sum, 1);
                    sum += __shfl_xor_sync(0xffffffffu, sum, 2);
                    l_i[g][rh] = l_i[g][rh] * f + sum;
                    m_i[g][rh] = mnew;
#pragma unroll
                    for (int ni = 0; ni < 8; ni++) {
                        oacc[g][ni][rh * 2]     *= f;
                        oacc[g][ni][rh * 2 + 1] *= f;
                    }
                }

                // ---- write P (warp-private rows) ----
#pragma unroll
                for (int ni = 0; ni < 8; ni++)
#pragma unroll
                    for (int rh = 0; rh < 2; rh++) {
                        int row = w * 32 + g * 16 + lg + rh * 8;
                        int c = ni * 2 + (lt >> 1);
                        sts64v(sb + AT_P + row * 256 + swz(row, c) + (lt & 1) * 8,
                               f2tf32(sc[ni][rh * 2]), f2tf32(sc[ni][rh * 2 + 1]));
                    }
            }
            __syncwarp();

            // ---- O += P @ V (V fragments shared across both groups) ----
#pragma unroll
            for (int ks = 0; ks < 8; ks++) {
                uint32_t pa[2][4];
#pragma unroll
                for (int g = 0; g < 2; g++) {
                    int row = w * 32 + g * 16 + arow_l;
                    ldsm4(pa[g], sb + AT_P + row * 256 + swz(row, 2 * ks + ach));
                }
#pragma unroll
                for (int n2 = 0; n2 < 4; n2++) {
                    uint32_t vf[4];
                    int vr = n2 * 16 + brow_base;
                    ldsm4(vf, so + AT_V + vr * 256 + swz(vr, 2 * ks + bch));
#pragma unroll
                    for (int g = 0; g < 2; g++) {
                        mma_tf32(oacc[g][2 * n2],     pa[g], &vf[0]);
                        mma_tf32(oacc[g][2 * n2 + 1], pa[g], &vf[2]);
                    }
                }
            }
            __syncwarp();
        }
    }

    // ---- epilogue: normalize, round, write [B,S,E] ----
    const int b = bh >> 4;
    const int h = bh & 15;
#pragma unroll
    for (int g = 0; g < 2; g++)
#pragma unroll
        for (int rh = 0; rh < 2; rh++) {
            float inv = 1.f / l_i[g][rh];
#pragma unroll
            for (int ni = 0; ni < 8; ni++) {
                int s = q0 + w * 32 + g * 16 + lg + rh * 8;
                int e = h * 64 + ni * 8 + lt * 2;
                float2 v;
                v.x = __uint_as_float(f2tf32(oacc[g][ni][rh * 2]     * inv));
                v.y = __uint_as_float(f2tf32(oacc[g][ni][rh * 2 + 1] * inv));
                *(float2*)(g_attn + (size_t)(b * SS + s) * EE + e) = v;
            }
        }
}

// ---------------------------------------------------------------------------
// Launch
// ---------------------------------------------------------------------------
extern "C" void kernel_launch(void* const* d_in, const int* in_sizes, int n_in,
                              void* d_out, int out_size)
{
    const float* x  = (const float*)d_in[0];
    const float* Wq = (const float*)d_in[1];
    const float* bq = (const float*)d_in[2];
    const float* Wk = (const float*)d_in[3];
    const float* bk = (const float*)d_in[4];
    const float* Wv = (const float*)d_in[5];
    const float* bv = (const float*)d_in[6];
    const float* Wo = (const float*)d_in[7];
    const float* bo = (const float*)d_in[8];
    float* out = (float*)d_out;

    (void)cudaFuncSetAttribute(qkv_mma,
                               cudaFuncAttributeMaxDynamicSharedMemorySize,
                               GEMM_SMEM);
    (void)cudaFuncSetAttribute(proj_mma,
                               cudaFuncAttributeMaxDynamicSharedMemorySize,
                               GEMM_SMEM);
    (void)cudaFuncSetAttribute(attn_kernel,
                               cudaFuncAttributeMaxDynamicSharedMemorySize,
                               ATTN_SMEM_BYTES);

    prep_x<<<1024, 256>>>(x);
    prep_w<<<dim3(32, 32, 4), 256>>>(Wq, Wk, Wv, Wo);

    dim3 gq(EE / GBN, NTOK / GBM, 3);
    qkv_mma<<<gq, 256, GEMM_SMEM>>>(bq, bk, bv);

    dim3 ga(SS / 128, BB * HH);
    attn_kernel<<<ga, 128, ATTN_SMEM_BYTES>>>();

    dim3 gp(EE / GBN, NTOK / GBM);
    proj_mma<<<gp, 256, GEMM_SMEM>>>(bo, out);
}

// round 11
// speedup vs baseline: 4.2000x; 1.0121x over previous
#include <cuda_runtime.h>
#include <math.h>
#include <stdint.h>

// Problem constants
#define BB   2
#define SS   2048
#define EE   1024
#define HH   16
#define DD   64
#define NTOK (BB * SS)   // 4096

// GEMM tiling: CTA 128x256xk32, 8 warps, warp tile 64x64
#define GBM 128
#define GBN 256
#define GBK 32
#define GNIT (EE / GBK)                 // 32
#define NSTG 3
#define A_BYTES (GBM * 128)             // 16384
#define B_BYTES (GBN * 128)             // 32768
#define STG_BYTES (A_BYTES + B_BYTES)   // 49152
#define GEMM_SMEM (NSTG * STG_BYTES)    // 147456

// Attention: CTA q-tile 128, kv-tile 64, 4 warps (32 q-rows each)
// smem: [stage0: K 16K | V 16K][stage1: K 16K | V 16K][Q/P 32K] = 96KB
#define AT_STG 32768
#define AT_V   16384
#define AT_P   65536
#define ATTN_SMEM_BYTES 98304

// ---------------------------------------------------------------------------
// Scratch
// ---------------------------------------------------------------------------
__device__ float g_x[NTOK * EE];             // x, tf32-rounded
__device__ float g_wt[4 * EE * EE];          // Wq^T,Wk^T,Wv^T,Wo^T, rounded
__device__ float g_q[BB * HH * SS * DD];     // [B,H,S,D]
__device__ float g_k[BB * HH * SS * DD];     // [B,H,S,D], tf32-rounded
__device__ float g_v[BB * HH * SS * DD];     // [B,H,D,S] transposed, rounded
__device__ float g_attn[NTOK * EE];          // [B,S,E], tf32-rounded

// ---------------------------------------------------------------------------
// helpers
// ---------------------------------------------------------------------------
__device__ __forceinline__ uint32_t f2tf32(float f)
{
    uint32_t u;
    asm("cvt.rna.tf32.f32 %0, %1;" : "=r"(u) : "f"(f));
    return u;
}

__device__ __forceinline__ uint4 pack_tf32(float4 v)
{
    uint4 u;
    u.x = f2tf32(v.x); u.y = f2tf32(v.y); u.z = f2tf32(v.z); u.w = f2tf32(v.w);
    return u;
}

__device__ __forceinline__ void mma_tf32(float c[4], const uint32_t a[4],
                                         const uint32_t b[2])
{
    asm volatile(
        "mma.sync.aligned.m16n8k8.row.col.f32.tf32.tf32.f32 "
        "{%0,%1,%2,%3}, {%4,%5,%6,%7}, {%8,%9}, {%0,%1,%2,%3};"
        : "+f"(c[0]), "+f"(c[1]), "+f"(c[2]), "+f"(c[3])
        : "r"(a[0]), "r"(a[1]), "r"(a[2]), "r"(a[3]), "r"(b[0]), "r"(b[1]));
}

__device__ __forceinline__ uint32_t s2u(const void* p)
{
    return (uint32_t)__cvta_generic_to_shared(p);
}

__device__ __forceinline__ void cpa16(uint32_t dst, const void* src)
{
    asm volatile("cp.async.cg.shared.global [%0], [%1], 16;"
                 :: "r"(dst), "l"(src) : "memory");
}
__device__ __forceinline__ void cpa_commit()
{
    asm volatile("cp.async.commit_group;" ::: "memory");
}
__device__ __forceinline__ void cpa_wait1()
{
    asm volatile("cp.async.wait_group 1;" ::: "memory");
}
__device__ __forceinline__ void cpa_wait0()
{
    asm volatile("cp.async.wait_group 0;" ::: "memory");
}

__device__ __forceinline__ void ldsm4(uint32_t* r, uint32_t a)
{
    asm volatile("ldmatrix.sync.aligned.m8n8.x4.shared.b16 {%0,%1,%2,%3}, [%4];"
                 : "=r"(r[0]), "=r"(r[1]), "=r"(r[2]), "=r"(r[3]) : "r"(a));
}

__device__ __forceinline__ void sts128(uint32_t a, uint4 v)
{
    asm volatile("st.shared.v4.b32 [%0], {%1,%2,%3,%4};"
                 :: "r"(a), "r"(v.x), "r"(v.y), "r"(v.z), "r"(v.w) : "memory");
}

__device__ __forceinline__ void sts64v(uint32_t a, uint32_t x, uint32_t y)
{
    asm volatile("st.shared.v2.b32 [%0], {%1,%2};"
                 :: "r"(a), "r"(x), "r"(y) : "memory");
}

// 16B-chunk swizzle within rows of 256B: chunk' = ((c&7)^(row&7)) | (c&8)
__device__ __forceinline__ uint32_t swz(int row, int c)
{
    return (uint32_t)(((((c) & 7) ^ ((row) & 7)) | ((c) & 8)) << 4);
}

// fast 2^x on the FMA pipe (x <= 0; rel err ~4e-5)
__device__ __forceinline__ float fexp2(float x)
{
    x = fmaxf(x, -100.f);
    float z = x + 12582912.f;
    float f = x - (z - 12582912.f);
    float p = fmaf(f, 0.009618129f, 0.055504109f);
    p = fmaf(f, p, 0.240226507f);
    p = fmaf(f, p, 0.693147181f);
    p = fmaf(f, p, 1.0f);
    int e = (int)((unsigned)__float_as_int(z) << 23);
    return __int_as_float(__float_as_int(p) + e);
}

// ---------------------------------------------------------------------------
// Pre-pass: round x -> g_x
// ---------------------------------------------------------------------------
__global__ void __launch_bounds__(256)
prep_x(const float* __restrict__ x)
{
    const int i = blockIdx.x * 256 + threadIdx.x;
#pragma unroll
    for (int j = 0; j < 4; j++) {
        int idx = i + j * 262144;
        float4 v = ((const float4*)x)[idx];
        uint4 u = pack_tf32(v);
        float4 o;
        o.x = __uint_as_float(u.x); o.y = __uint_as_float(u.y);
        o.z = __uint_as_float(u.z); o.w = __uint_as_float(u.w);
        ((float4*)g_x)[idx] = o;
    }
}

// ---------------------------------------------------------------------------
// Pre-pass: transpose + round W -> g_wt
// ---------------------------------------------------------------------------
__global__ void __launch_bounds__(256)
prep_w(const float* __restrict__ Wq, const float* __restrict__ Wk,
       const float* __restrict__ Wv, const float* __restrict__ Wo)
{
    __shared__ float t[32][33];
    const float* W;
    if (blockIdx.z == 0)      W = Wq;
    else if (blockIdx.z == 1) W = Wk;
    else if (blockIdx.z == 2) W = Wv;
    else                      W = Wo;
    float* out = g_wt + (size_t)blockIdx.z * EE * EE;

    const int n0 = blockIdx.x * 32, k0 = blockIdx.y * 32;
    const int x = threadIdx.x & 31, y = threadIdx.x >> 5;
#pragma unroll
    for (int i = 0; i < 4; i++)
        t[y + 8 * i][x] = W[(size_t)(k0 + y + 8 * i) * EE + n0 + x];
    __syncthreads();
#pragma unroll
    for (int i = 0; i < 4; i++)
        out[(size_t)(n0 + y + 8 * i) * EE + k0 + x] =
            __uint_as_float(f2tf32(t[x][y + 8 * i]));
}

// ---------------------------------------------------------------------------
// GEMM core: C[128x256] = A[.,1024] @ Bt^T.
// Linear (base+stride) cp.async addressing; fragment double buffering.
// ---------------------------------------------------------------------------
__device__ __forceinline__ void gemm_core(const float* __restrict__ A,
                                          const float* __restrict__ Bt,
                                          int brow, int bcol,
                                          float c[4][8][4], char* sm)
{
    const int tid = threadIdx.x;
    const int w = tid >> 5, l = tid & 31;
    const int wm = w >> 2, wn = w & 3;
    const uint32_t sb = s2u(sm);

    // Linear cp.async mappings: row/n stride 32 per j (row&7 invariant -> swz fixed)
    const int r0 = tid >> 3;                 // A row / B n base
    const int kc = tid & 7;                  // 16B chunk
    const float* asrc0 = A + (size_t)(brow + r0) * EE + kc * 4;
    const uint32_t adst0 = (uint32_t)(r0 * 128 + ((kc ^ (r0 & 7)) << 4));
    const float* bsrc0 = Bt + (size_t)(bcol + r0) * EE + kc * 4;
    const uint32_t bdst0 = (uint32_t)(A_BYTES + r0 * 128 + ((kc ^ (r0 & 7)) << 4));

#pragma unroll
    for (int mi = 0; mi < 4; mi++)
#pragma unroll
        for (int ni = 0; ni < 8; ni++)
#pragma unroll
            for (int r = 0; r < 4; r++) c[mi][ni][r] = 0.f;

#pragma unroll
    for (int s = 0; s < 2; s++) {
        uint32_t so = sb + s * STG_BYTES;
        int k0 = s * GBK;
#pragma unroll
        for (int j = 0; j < 4; j++)
            cpa16(so + adst0 + j * 4096, asrc0 + (size_t)j * 32 * EE + k0);
#pragma unroll
        for (int j = 0; j < 8; j++)
            cpa16(so + bdst0 + j * 4096, bsrc0 + (size_t)j * 32 * EE + k0);
        cpa_commit();
    }

    const uint32_t abase = (uint32_t)((wm * 64 + (l & 15)) * 128);
    const int ahalf = l >> 4;
    const int axor = l & 7;
    const uint32_t bbase = (uint32_t)(A_BYTES +
                          (wn * 64 + (l & 7) + ((l >> 4) << 3)) * 128);
    const int bhalf = (l >> 3) & 1;
    const int bxor = l & 7;

    int stage = 0;
    for (int it = 0; it < GNIT; it++) {
        cpa_wait1();
        __syncthreads();

        if (it + 2 < GNIT) {
            int ls = (stage + 2) % NSTG;
            uint32_t so = sb + ls * STG_BYTES;
            int k0 = (it + 2) * GBK;
#pragma unroll
            for (int j = 0; j < 4; j++)
                cpa16(so + adst0 + j * 4096, asrc0 + (size_t)j * 32 * EE + k0);
#pragma unroll
            for (int j = 0; j < 8; j++)
                cpa16(so + bdst0 + j * 4096, bsrc0 + (size_t)j * 32 * EE + k0);
        }
        cpa_commit();

        const uint32_t so = sb + stage * STG_BYTES;

        // fragment double buffering across the 4 k-slices
        uint32_t af[2][4][4], bf[2][4][4];
#pragma unroll
        for (int mi = 0; mi < 4; mi++)
            ldsm4(af[0][mi], so + abase + mi * 2048 +
                  ((uint32_t)((ahalf) ^ axor) << 4));
#pragma unroll
        for (int n2 = 0; n2 < 4; n2++)
            ldsm4(bf[0][n2], so + bbase + n2 * 2048 +
                  ((uint32_t)((bhalf) ^ bxor) << 4));

#pragma unroll
        for (int ks = 0; ks < 4; ks++) {
            const int cur = ks & 1;
            if (ks < 3) {
                const int nxt = cur ^ 1;
#pragma unroll
                for (int mi = 0; mi < 4; mi++)
                    ldsm4(af[nxt][mi], so + abase + mi * 2048 +
                          ((uint32_t)((2 * (ks + 1) + ahalf) ^ axor) << 4));
#pragma unroll
                for (int n2 = 0; n2 < 4; n2++)
                    ldsm4(bf[nxt][n2], so + bbase + n2 * 2048 +
                          ((uint32_t)((2 * (ks + 1) + bhalf) ^ bxor) << 4));
            }
#pragma unroll
            for (int mi = 0; mi < 4; mi++)
#pragma unroll
                for (int n2 = 0; n2 < 4; n2++) {
                    mma_tf32(c[mi][2 * n2],     af[cur][mi], &bf[cur][n2][0]);
                    mma_tf32(c[mi][2 * n2 + 1], af[cur][mi], &bf[cur][n2][2]);
                }
        }
        stage = (stage + 1) % NSTG;
    }
}

// ---------------------------------------------------------------------------
// QKV: grid (4, 32, 3). K and V written tf32-pre-rounded (cp.async-ready).
// ---------------------------------------------------------------------------
__global__ void __launch_bounds__(256, 1)
qkv_mma(const float* __restrict__ bq, const float* __restrict__ bk,
        const float* __restrict__ bv)
{
    extern __shared__ char smc[];
    const float* bias;
    if (blockIdx.z == 0)      bias = bq;
    else if (blockIdx.z == 1) bias = bk;
    else                      bias = bv;
    const float* Bt = g_wt + (size_t)blockIdx.z * EE * EE;

    const int brow = blockIdx.y * GBM;
    const int bcol = blockIdx.x * GBN;

    float c[4][8][4];
    gemm_core(g_x, Bt, brow, bcol, c, smc);

    const int tid = threadIdx.x;
    const int w = tid >> 5, l = tid & 31;
    const int wm = w >> 2, wn = w & 3;

#pragma unroll
    for (int mi = 0; mi < 4; mi++)
#pragma unroll
        for (int ni = 0; ni < 8; ni++) {
            int row0 = brow + wm * 64 + mi * 16 + (l >> 2);
            int col  = bcol + wn * 64 + ni * 8 + (l & 3) * 2;
            float b0 = bias[col], b1 = bias[col + 1];
            int h = col >> 6, d = col & 63;
#pragma unroll
            for (int half = 0; half < 2; half++) {
                int t = row0 + half * 8;
                int b = t >> 11, s = t & 2047;
                float v0 = c[mi][ni][half * 2 + 0] + b0;
                float v1 = c[mi][ni][half * 2 + 1] + b1;
                if (blockIdx.z == 0) {
                    float2 v; v.x = v0; v.y = v1;
                    *(float2*)(g_q + ((size_t)(b * HH + h) * SS + s) * DD + d) = v;
                } else if (blockIdx.z == 1) {
                    float2 v;
                    v.x = __uint_as_float(f2tf32(v0));
                    v.y = __uint_as_float(f2tf32(v1));
                    *(float2*)(g_k + ((size_t)(b * HH + h) * SS + s) * DD + d) = v;
                } else {
                    size_t base = (size_t)(b * HH + h) * DD;
                    g_v[(base + d)     * SS + s] = __uint_as_float(f2tf32(v0));
                    g_v[(base + d + 1) * SS + s] = __uint_as_float(f2tf32(v1));
                }
            }
        }
}

// ---------------------------------------------------------------------------
// Out-proj: grid (4, 32)
// ---------------------------------------------------------------------------
__global__ void __launch_bounds__(256, 1)
proj_mma(const float* __restrict__ bo, float* __restrict__ out)
{
    extern __shared__ char smc[];
    const float* Bt = g_wt + (size_t)3 * EE * EE;

    const int brow = blockIdx.y * GBM;
    const int bcol = blockIdx.x * GBN;

    float c[4][8][4];
    gemm_core(g_attn, Bt, brow, bcol, c, smc);

    const int tid = threadIdx.x;
    const int w = tid >> 5, l = tid & 31;
    const int wm = w >> 2, wn = w & 3;

#pragma unroll
    for (int mi = 0; mi < 4; mi++)
#pragma unroll
        for (int ni = 0; ni < 8; ni++) {
            int row0 = brow + wm * 64 + mi * 16 + (l >> 2);
            int col  = bcol + wn * 64 + ni * 8 + (l & 3) * 2;
            float b0 = bo[col], b1 = bo[col + 1];
#pragma unroll
            for (int half = 0; half < 2; half++) {
                int row = row0 + half * 8;
                float2 v;
                v.x = c[mi][ni][half * 2 + 0] + b0;
                v.y = c[mi][ni][half * 2 + 1] + b1;
                *(float2*)(out + (size_t)row * EE + col) = v;
            }
        }
}

// ---------------------------------------------------------------------------
// Flash attention v2: CTA q-tile 128, kv-tile 64, 4 warps x 32 q-rows.
// Linear cp.async addressing (no pointer arrays); otherwise as R10.
// grid (16, 32): x -> qt (reversed), y -> bh.
// ---------------------------------------------------------------------------
__global__ void __launch_bounds__(128, 2)
attn_kernel()
{
    extern __shared__ char smc[];
    const uint32_t sb = s2u(smc);

    const int tid = threadIdx.x;
    const int w = tid >> 5, l = tid & 31;
    const int lg = l >> 2, lt = l & 3;
    const int qt = (gridDim.x - 1) - blockIdx.x;
    const int bh = blockIdx.y;
    const int q0 = qt * 128;

    const float* Qg = g_q + (size_t)bh * SS * DD;
    const float* Kg = g_k + (size_t)bh * SS * DD;
    const float* Vg = g_v + (size_t)bh * DD * SS;   // [D,S]

    const int jmax = 2 * qt + 2;

    // Linear cp.async mappings: row stride 8 per j2 (row&7 invariant)
    const int kr0 = tid >> 4;            // base row
    const int kc4 = tid & 15;            // 16B chunk
    const float* ksrc0 = Kg + (size_t)kr0 * DD + kc4 * 4;
    const float* vsrc0 = Vg + (size_t)kr0 * SS + kc4 * 4;
    const uint32_t kdst0 = (uint32_t)(kr0 * 256 + swz(kr0, kc4));
    const uint32_t vdst0 = (uint32_t)(AT_V + kr0 * 256 + swz(kr0, kc4));

    // prologue: fetch kv-tile 0 into stage 0
#pragma unroll
    for (int j2 = 0; j2 < 8; j2++) {
        cpa16(sb + kdst0 + j2 * 2048, ksrc0 + (size_t)j2 * 8 * DD);
        cpa16(sb + vdst0 + j2 * 2048, vsrc0 + (size_t)j2 * 8 * SS);
    }
    cpa_commit();

    // load Q tile (scaled + rounded) into P region, hoist fragments
    const float qscale = 0.125f * 1.44269504f;
#pragma unroll
    for (int j = 0; j < 16; j++) {
        int p = tid + 128 * j;
        int r = p >> 4, c4 = p & 15;
        float4 v = *(const float4*)(Qg + (size_t)(q0 + r) * DD + c4 * 4);
        v.x *= qscale; v.y *= qscale; v.z *= qscale; v.w *= qscale;
        sts128(sb + AT_P + r * 256 + swz(r, c4), pack_tf32(v));
    }
    __syncthreads();

    const int arow_l = l & 15;
    const int ach = l >> 4;
    uint32_t qa[2][8][4];
#pragma unroll
    for (int g = 0; g < 2; g++) {
        int row = w * 32 + g * 16 + arow_l;
#pragma unroll
        for (int ks = 0; ks < 8; ks++)
            ldsm4(qa[g][ks], sb + AT_P + row * 256 + swz(row, 2 * ks + ach));
    }

    const int brow_base = (l & 7) + ((l >> 4) << 3);
    const int bch = (l >> 3) & 1;

    float m_i[2][2], l_i[2][2];
#pragma unroll
    for (int g = 0; g < 2; g++)
#pragma unroll
        for (int rh = 0; rh < 2; rh++) { m_i[g][rh] = -1e30f; l_i[g][rh] = 0.f; }

    float oacc[2][8][4];
#pragma unroll
    for (int g = 0; g < 2; g++)
#pragma unroll
        for (int ni = 0; ni < 8; ni++)
#pragma unroll
            for (int r = 0; r < 4; r++) oacc[g][ni][r] = 0.f;

    for (int j = 0; j < jmax; j++) {
        const int k0 = j * 64;
        const uint32_t so = sb + (j & 1) * AT_STG;

        cpa_wait0();
        __syncthreads();   // kv tile j visible; all warps done with other stage

        if (j + 1 < jmax) {
            const uint32_t sn = sb + ((j + 1) & 1) * AT_STG;
            const size_t knK = (size_t)(j + 1) * 64 * DD;
            const int knV = (j + 1) * 64;
#pragma unroll
            for (int j2 = 0; j2 < 8; j2++) {
                cpa16(sn + kdst0 + j2 * 2048, ksrc0 + (size_t)j2 * 8 * DD + knK);
                cpa16(sn + vdst0 + j2 * 2048, vsrc0 + (size_t)j2 * 8 * SS + knV);
            }
        }
        cpa_commit();

        // warp active if any of its rows can attend this kv tile
        const bool active = (k0 <= q0 + w * 32 + 31);
        if (active) {
#pragma unroll
            for (int g = 0; g < 2; g++) {
                // ---- S = Q @ K^T for this 16-row group ----
                float sc[8][4];
#pragma unroll
                for (int ni = 0; ni < 8; ni++)
#pragma unroll
                    for (int r = 0; r < 4; r++) sc[ni][r] = 0.f;

#pragma unroll
                for (int ks = 0; ks < 8; ks++) {
#pragma unroll
                    for (int n2 = 0; n2 < 4; n2++) {
                        uint32_t kf[4];
                        int br = n2 * 16 + brow_base;
                        ldsm4(kf, so + br * 256 + swz(br, 2 * ks + bch));
                        mma_tf32(sc[2 * n2],     qa[g][ks], &kf[0]);
                        mma_tf32(sc[2 * n2 + 1], qa[g][ks], &kf[2]);
                    }
                }

                // ---- causal mask (only possible on the last two tiles) ----
                if (j >= 2 * qt) {
#pragma unroll
                    for (int ni = 0; ni < 8; ni++)
#pragma unroll
                        for (int r = 0; r < 4; r++) {
                            int row = q0 + w * 32 + g * 16 + lg + (r >> 1) * 8;
                            int col = k0 + ni * 8 + lt * 2 + (r & 1);
                            if (col > row) sc[ni][r] = -1e30f;
                        }
                }

                // ---- online softmax (base 2, hybrid exp) ----
#pragma unroll
                for (int rh = 0; rh < 2; rh++) {
                    float m = -1e30f;
#pragma unroll
                    for (int ni = 0; ni < 8; ni++) {
                        m = fmaxf(m, sc[ni][rh * 2]);
                        m = fmaxf(m, sc[ni][rh * 2 + 1]);
                    }
                    m = fmaxf(m, __shfl_xor_sync(0xffffffffu, m, 1));
                    m = fmaxf(m, __shfl_xor_sync(0xffffffffu, m, 2));
                    float mnew = fmaxf(m_i[g][rh], m);
                    float f = exp2f(m_i[g][rh] - mnew);
                    float sum = 0.f;
#pragma unroll
                    for (int ni = 0; ni < 8; ni++) {
                        float x0 = sc[ni][rh * 2]     - mnew;
                        float x1 = sc[ni][rh * 2 + 1] - mnew;
                        float p0, p1;
                        if (ni < 6) { p0 = exp2f(x0); p1 = exp2f(x1); }
                        else        { p0 = fexp2(x0); p1 = fexp2(x1); }
                        sc[ni][rh * 2]     = p0;
                        sc[ni][rh * 2 + 1] = p1;
                        sum += p0 + p1;
                    }
                    sum += __shfl_xor_sync(0xffffffffu, sum, 1);
                    sum += __shfl_xor_sync(0xffffffffu, sum, 2);
                    l_i[g][rh] = l_i[g][rh] * f + sum;
                    m_i[g][rh] = mnew;
#pragma unroll
                    for (int ni = 0; ni < 8; ni++) {
                        oacc[g][ni][rh * 2]     *= f;
                        oacc[g][ni][rh * 2 + 1] *= f;
                    }
                }

                // ---- write P (warp-private rows) ----
#pragma unroll
                for (int ni = 0; ni < 8; ni++)
#pragma unroll
                    for (int rh = 0; rh < 2; rh++) {
                        int row = w * 32 + g * 16 + lg + rh * 8;
                        int c = ni * 2 + (lt >> 1);
                        sts64v(sb + AT_P + row * 256 + swz(row, c) + (lt & 1) * 8,
                               f2tf32(sc[ni][rh * 2]), f2tf32(sc[ni][rh * 2 + 1]));
                    }
            }
            __syncwarp();

            // ---- O += P @ V (V fragments shared across both groups) ----
#pragma unroll
            for (int ks = 0; ks < 8; ks++) {
                uint32_t pa[2][4];
#pragma unroll
                for (int g = 0; g < 2; g++) {
                    int row = w * 32 + g * 16 + arow_l;
                    ldsm4(pa[g], sb + AT_P + row * 256 + swz(row, 2 * ks + ach));
                }
#pragma unroll
                for (int n2 = 0; n2 < 4; n2++) {
                    uint32_t vf[4];
                    int vr = n2 * 16 + brow_base;
                    ldsm4(vf, so + AT_V + vr * 256 + swz(vr, 2 * ks + bch));
#pragma unroll
                    for (int g = 0; g < 2; g++) {
                        mma_tf32(oacc[g][2 * n2],     pa[g], &vf[0]);
                        mma_tf32(oacc[g][2 * n2 + 1], pa[g], &vf[2]);
                    }
                }
            }
            __syncwarp();
        }
    }

    // ---- epilogue: normalize, round, write [B,S,E] ----
    const int b = bh >> 4;
    const int h = bh & 15;
#pragma unroll
    for (int g = 0; g < 2; g++)
#pragma unroll
        for (int rh = 0; rh < 2; rh++) {
            float inv = 1.f / l_i[g][rh];
#pragma unroll
            for (int ni = 0; ni < 8; ni++) {
                int s = q0 + w * 32 + g * 16 + lg + rh * 8;
                int e = h * 64 + ni * 8 + lt * 2;
                float2 v;
                v.x = __uint_as_float(f2tf32(oacc[g][ni][rh * 2]     * inv));
                v.y = __uint_as_float(f2tf32(oacc[g][ni][rh * 2 + 1] * inv));
                *(float2*)(g_attn + (size_t)(b * SS + s) * EE + e) = v;
            }
        }
}

// ---------------------------------------------------------------------------
// Launch
// ---------------------------------------------------------------------------
extern "C" void kernel_launch(void* const* d_in, const int* in_sizes, int n_in,
                              void* d_out, int out_size)
{
    const float* x  = (const float*)d_in[0];
    const float* Wq = (const float*)d_in[1];
    const float* bq = (const float*)d_in[2];
    const float* Wk = (const float*)d_in[3];
    const float* bk = (const float*)d_in[4];
    const float* Wv = (const float*)d_in[5];
    const float* bv = (const float*)d_in[6];
    const float* Wo = (const float*)d_in[7];
    const float* bo = (const float*)d_in[8];
    float* out = (float*)d_out;

    (void)cudaFuncSetAttribute(qkv_mma,
                               cudaFuncAttributeMaxDynamicSharedMemorySize,
                               GEMM_SMEM);
    (void)cudaFuncSetAttribute(proj_mma,
                               cudaFuncAttributeMaxDynamicSharedMemorySize,
                               GEMM_SMEM);
    (void)cudaFuncSetAttribute(attn_kernel,
                               cudaFuncAttributeMaxDynamicSharedMemorySize,
                               ATTN_SMEM_BYTES);

    prep_x<<<1024, 256>>>(x);
    prep_w<<<dim3(32, 32, 4), 256>>>(Wq, Wk, Wv, Wo);

    dim3 gq(EE / GBN, NTOK / GBM, 3);
    qkv_mma<<<gq, 256, GEMM_SMEM>>>(bq, bk, bv);

    dim3 ga(SS / 128, BB * HH);
    attn_kernel<<<ga, 128, ATTN_SMEM_BYTES>>>();

    dim3 gp(EE / GBN, NTOK / GBM);
    proj_mma<<<gp, 256, GEMM_SMEM>>>(bo, out);
}